// round 8
// baseline (speedup 1.0000x reference)
#include <cuda_runtime.h>
#include <cuda_bf16.h>
#include <math.h>
#include <stdint.h>

// ---------------------------------------------------------------------------
// Problem constants
// ---------------------------------------------------------------------------
#define Bm 256
#define Lm 200
#define Hm 768
#define Dm 64
#define NS 6
#define Mseq (Bm * Lm)          // 51200
#define NC 8                    // scan chunks
#define CL 25                   // Lm / NC

typedef unsigned long long ull;

// ---------------------------------------------------------------------------
// Device scratch (static globals — no allocation allowed)
// ---------------------------------------------------------------------------
__device__ float g_E[(size_t)Mseq * Dm];            // E = ev@We+be
__device__ float g_G[(size_t)6 * Mseq * Dm];        // activated gates (gate, row, d)
__device__ float g_Hs[(size_t)Mseq * Dm];           // hidden states
__device__ float g_Ec[Bm * Dm];
__device__ float g_Gc[6 * Bm * Dm];
__device__ float g_Clast[Bm * Dm];
__device__ float g_Hcur[Bm * Dm];
__device__ float g_wt[384];                          // Wtime @ Wg_bot
__device__ float g_bias[384];                        // btime @ Wg_bot + bg
__device__ float g_scanP[Bm * Dm * NC];              // chunk prod(f)
__device__ float g_scanA[Bm * Dm * NC];              // chunk affine term
__device__ float g_scanCin[Bm * Dm * NC];            // chunk entry carry
__device__ unsigned g_WeHi[384 * 64];                // We split: packed bf16x2 (k pairs)
__device__ unsigned g_WeLo[384 * 64];

// ---------------------------------------------------------------------------
// Math helpers
// ---------------------------------------------------------------------------
__device__ __forceinline__ float fast_tanh(float x) {
    float y;
    asm("tanh.approx.f32 %0, %1;" : "=f"(y) : "f"(x));
    return y;
}
__device__ __forceinline__ float fsigmoid(float x) {
    return __fdividef(1.0f, 1.0f + __expf(-x));
}
__device__ __forceinline__ float fsoftplus(float x) {
    return fmaxf(x, 0.0f) + log1pf(__expf(-fabsf(x)));
}
__device__ __forceinline__ float fgelu(float x) {
    return 0.5f * x * (1.0f + erff(x * 0.70710678118654752f));
}
// pack two f32 -> bf16x2 (lo = first element in lower 16 bits)
__device__ __forceinline__ unsigned bfpair(float lo, float hi) {
    unsigned r;
    asm("cvt.rn.bf16x2.f32 %0, %1, %2;" : "=r"(r) : "f"(hi), "f"(lo));
    return r;
}
// split a float2 (consecutive-k pair) into hi/lo bf16x2 regs
__device__ __forceinline__ void split2(float2 e, unsigned& h, unsigned& l) {
    unsigned hp = bfpair(e.x, e.y);
    float h0 = __uint_as_float(hp << 16);
    float h1 = __uint_as_float(hp & 0xFFFF0000u);
    h = hp;
    l = bfpair(e.x - h0, e.y - h1);
}
__device__ __forceinline__ void mma_bf16(float* c, const unsigned* a, unsigned b0, unsigned b1) {
    asm volatile(
        "mma.sync.aligned.m16n8k16.row.col.f32.bf16.bf16.f32 "
        "{%0,%1,%2,%3}, {%4,%5,%6,%7}, {%8,%9}, {%0,%1,%2,%3};"
        : "+f"(c[0]), "+f"(c[1]), "+f"(c[2]), "+f"(c[3])
        : "r"(a[0]), "r"(a[1]), "r"(a[2]), "r"(a[3]), "r"(b0), "r"(b1));
}

// ---------------------------------------------------------------------------
// Setup: wt[c] = sum_d Wtime[d]*Wg[64+d,c]; bias[c] = sum_d btime[d]*Wg[64+d,c] + bg[c]
// ---------------------------------------------------------------------------
__global__ void setup_kernel(const float* __restrict__ Wtime, const float* __restrict__ btime,
                             const float* __restrict__ Wg, const float* __restrict__ bg) {
    int c = threadIdx.x;   // 384 threads
    float s1 = 0.f, s2 = 0.f;
    #pragma unroll 8
    for (int d = 0; d < 64; d++) {
        float w = Wg[(size_t)(64 + d) * 384 + c];
        s1 += Wtime[d] * w;
        s2 += btime[d] * w;
    }
    g_wt[c] = s1;
    g_bias[c] = s2 + bg[c];
}

// Split We[768,64] into packed bf16x2 hi/lo planes: index t = j*64+n, j=k/2.
__global__ void split_we_kernel(const float* __restrict__ We) {
    int t = blockIdx.x * 256 + threadIdx.x;   // 0..24575
    if (t >= 384 * 64) return;
    int j = t >> 6, n = t & 63;
    float e0 = We[(size_t)(2 * j) * 64 + n];
    float e1 = We[(size_t)(2 * j + 1) * 64 + n];
    unsigned hp = bfpair(e0, e1);
    float h0 = __uint_as_float(hp << 16);
    float h1 = __uint_as_float(hp & 0xFFFF0000u);
    g_WeHi[t] = hp;
    g_WeLo[t] = bfpair(e0 - h0, e1 - h1);
}

// ---------------------------------------------------------------------------
// GEMM1 via bf16-split tensor-core mma:
//   C[M,64] = A[M,768] @ We + be,  C ≈ Ahi@Whi + Ahi@Wlo + Alo@Whi (fp32 acc)
// CTA: 128 rows x 64 cols, 8 warps in 4x2 grid (warp = 32 rows x 32 cols),
// K chunks of 16, double-buffered smem.
// ---------------------------------------------------------------------------
__global__ __launch_bounds__(256) void gemm1_mma(const float* __restrict__ A,
                                                 const unsigned* __restrict__ BHi,
                                                 const unsigned* __restrict__ BLo,
                                                 const float* __restrict__ be,
                                                 float* __restrict__ C) {
    __shared__ __align__(16) float As[2][128][20];        // [m][k] + pad (80B rows, 16B-aligned)
    __shared__ __align__(16) unsigned BsH[2][8][64];      // [j][n] packed bf16x2
    __shared__ __align__(16) unsigned BsL[2][8][64];
    const int tid = threadIdx.x;
    const int wid = tid >> 5, lane = tid & 31;
    const int warpR = wid >> 1;          // 0..3 : rows warpR*32
    const int warpC = wid & 1;           // 0..1 : cols warpC*32
    const size_t r0 = (size_t)blockIdx.x * 128;
    const int q = lane & 3, rr = lane >> 2;

    float acc[2][4][4];
    #pragma unroll
    for (int mt = 0; mt < 2; mt++)
        #pragma unroll
        for (int nt = 0; nt < 4; nt++)
            #pragma unroll
            for (int i = 0; i < 4; i++) acc[mt][nt][i] = 0.f;

    // tile 0 loads
    {
        #pragma unroll
        for (int p = 0; p < 2; p++) {
            int idx = tid + p * 256;
            int m = idx >> 2, kv = (idx & 3) * 4;
            *reinterpret_cast<float4*>(&As[0][m][kv]) =
                *reinterpret_cast<const float4*>(A + (r0 + m) * 768 + kv);
        }
        *reinterpret_cast<uint2*>(&BsH[0][0][0] + tid * 2) =
            *reinterpret_cast<const uint2*>(BHi + tid * 2);
        *reinterpret_cast<uint2*>(&BsL[0][0][0] + tid * 2) =
            *reinterpret_cast<const uint2*>(BLo + tid * 2);
    }
    __syncthreads();

    #pragma unroll 2
    for (int t = 0; t < 48; t++) {
        int cur = t & 1;
        // prefetch next tile into other buffer
        if (t < 47) {
            int nxt = cur ^ 1;
            int k0 = (t + 1) * 16;
            #pragma unroll
            for (int p = 0; p < 2; p++) {
                int idx = tid + p * 256;
                int m = idx >> 2, kv = (idx & 3) * 4;
                *reinterpret_cast<float4*>(&As[nxt][m][kv]) =
                    *reinterpret_cast<const float4*>(A + (r0 + m) * 768 + k0 + kv);
            }
            size_t jb = (size_t)(t + 1) * 8 * 64;
            *reinterpret_cast<uint2*>(&BsH[nxt][0][0] + tid * 2) =
                *reinterpret_cast<const uint2*>(BHi + jb + tid * 2);
            *reinterpret_cast<uint2*>(&BsL[nxt][0][0] + tid * 2) =
                *reinterpret_cast<const uint2*>(BLo + jb + tid * 2);
        }

        // A fragments (hi/lo) for 2 m-tiles
        unsigned aH[2][4], aL[2][4];
        #pragma unroll
        for (int mt = 0; mt < 2; mt++) {
            int row = warpR * 32 + mt * 16 + rr;
            #pragma unroll
            for (int kk = 0; kk < 2; kk++) {
                float2 e0 = *reinterpret_cast<const float2*>(&As[cur][row][2 * q + 8 * kk]);
                float2 e1 = *reinterpret_cast<const float2*>(&As[cur][row + 8][2 * q + 8 * kk]);
                split2(e0, aH[mt][2 * kk + 0], aL[mt][2 * kk + 0]);
                split2(e1, aH[mt][2 * kk + 1], aL[mt][2 * kk + 1]);
            }
        }
        // per n-tile B fragments + 3-split mma
        #pragma unroll
        for (int nt = 0; nt < 4; nt++) {
            int c = warpC * 32 + nt * 8 + rr;
            unsigned bH0 = BsH[cur][q][c],     bH1 = BsH[cur][q + 4][c];
            unsigned bL0 = BsL[cur][q][c],     bL1 = BsL[cur][q + 4][c];
            #pragma unroll
            for (int mt = 0; mt < 2; mt++) {
                mma_bf16(acc[mt][nt], aH[mt], bH0, bH1);
                mma_bf16(acc[mt][nt], aH[mt], bL0, bL1);
                mma_bf16(acc[mt][nt], aL[mt], bH0, bH1);
            }
        }
        __syncthreads();
    }

    // epilogue: + be, direct float2 stores
    #pragma unroll
    for (int nt = 0; nt < 4; nt++) {
        int col = warpC * 32 + nt * 8 + 2 * q;
        float b0 = be[col], b1 = be[col + 1];
        #pragma unroll
        for (int mt = 0; mt < 2; mt++) {
            size_t row = r0 + warpR * 32 + mt * 16 + rr;
            *reinterpret_cast<float2*>(C + row * 64 + col) =
                make_float2(acc[mt][nt][0] + b0, acc[mt][nt][1] + b1);
            *reinterpret_cast<float2*>(C + (row + 8) * 64 + col) =
                make_float2(acc[mt][nt][2] + b0, acc[mt][nt][3] + b1);
        }
    }
}

// ---------------------------------------------------------------------------
// GEMM2: gates = act( E[M,64] @ Wg_top[64,384] + days[row]*wt + bias )
// (unchanged from R5 — measured 80.1us, ~87% of scalar-FFMA floor)
// ---------------------------------------------------------------------------
__device__ __forceinline__ void fma2(ull& d, ull a, ull b) {
    asm("fma.rn.f32x2 %0, %1, %2, %0;" : "+l"(d) : "l"(a), "l"(b));
}
__device__ __forceinline__ ull pack2(float x, float y) {
    ull r;
    asm("mov.b64 %0, {%1, %2};" : "=l"(r) : "f"(x), "f"(y));
    return r;
}
__device__ __forceinline__ float2 unpack2(ull v) {
    float2 r;
    asm("mov.b64 {%0, %1}, %2;" : "=f"(r.x), "=f"(r.y) : "l"(v));
    return r;
}

__global__ __launch_bounds__(256) void gemm2_kernel(const float* __restrict__ E,
                                                    const float* __restrict__ Wg,
                                                    const float* __restrict__ days,
                                                    float* __restrict__ gates, int M) {
    __shared__ __align__(16) float As[2][16][132];
    __shared__ __align__(16) float Bs[2][16][128];
    const int tid = threadIdx.x;
    const size_t r0 = (size_t)blockIdx.x * 128;
    const int n0 = blockIdx.y * 128;
    const int tm = tid >> 4;
    const int tn = tid & 15;

    ull acc[4][8];
    #pragma unroll
    for (int i = 0; i < 4; i++)
        #pragma unroll
        for (int j = 0; j < 8; j++) acc[i][j] = 0ull;

    float4 ra[2], rb[2];
    #pragma unroll
    for (int p = 0; p < 2; p++) {
        int idx = tid + p * 256;
        int m = idx >> 2, kv = (idx & 3) * 4;
        ra[p] = *reinterpret_cast<const float4*>(E + (r0 + m) * 64 + kv);
    }
    #pragma unroll
    for (int qq = 0; qq < 2; qq++) {
        int idx = tid + qq * 256;
        int k = idx >> 5, nv = (idx & 31) * 4;
        rb[qq] = *reinterpret_cast<const float4*>(Wg + (size_t)k * 384 + n0 + nv);
    }
    #pragma unroll
    for (int p = 0; p < 2; p++) {
        int idx = tid + p * 256;
        int m = idx >> 2, kv = (idx & 3) * 4;
        As[0][kv + 0][m] = ra[p].x; As[0][kv + 1][m] = ra[p].y;
        As[0][kv + 2][m] = ra[p].z; As[0][kv + 3][m] = ra[p].w;
    }
    #pragma unroll
    for (int qq = 0; qq < 2; qq++) {
        int idx = tid + qq * 256;
        int k = idx >> 5, nv = (idx & 31) * 4;
        *reinterpret_cast<float4*>(&Bs[0][k][nv]) = rb[qq];
    }
    __syncthreads();

    #pragma unroll 2
    for (int t = 0; t < 4; t++) {
        int cur = t & 1;
        if (t < 3) {
            int k0 = (t + 1) * 16;
            #pragma unroll
            for (int p = 0; p < 2; p++) {
                int idx = tid + p * 256;
                int m = idx >> 2, kv = (idx & 3) * 4;
                ra[p] = *reinterpret_cast<const float4*>(E + (r0 + m) * 64 + k0 + kv);
            }
            #pragma unroll
            for (int qq = 0; qq < 2; qq++) {
                int idx = tid + qq * 256;
                int k = idx >> 5, nv = (idx & 31) * 4;
                rb[qq] = *reinterpret_cast<const float4*>(Wg + (size_t)(k0 + k) * 384 + n0 + nv);
            }
        }
        #pragma unroll
        for (int kk = 0; kk < 16; kk++) {
            const ull* pa = reinterpret_cast<const ull*>(&As[cur][kk][tm * 8]);
            ull a0 = pa[0], a1 = pa[1], a2 = pa[2], a3 = pa[3];
            float4 bA = *reinterpret_cast<const float4*>(&Bs[cur][kk][tn * 8]);
            float4 bB = *reinterpret_cast<const float4*>(&Bs[cur][kk][tn * 8 + 4]);
            ull bp[8];
            bp[0] = pack2(bA.x, bA.x); bp[1] = pack2(bA.y, bA.y);
            bp[2] = pack2(bA.z, bA.z); bp[3] = pack2(bA.w, bA.w);
            bp[4] = pack2(bB.x, bB.x); bp[5] = pack2(bB.y, bB.y);
            bp[6] = pack2(bB.z, bB.z); bp[7] = pack2(bB.w, bB.w);
            #pragma unroll
            for (int j = 0; j < 8; j++) {
                fma2(acc[0][j], a0, bp[j]);
                fma2(acc[1][j], a1, bp[j]);
                fma2(acc[2][j], a2, bp[j]);
                fma2(acc[3][j], a3, bp[j]);
            }
        }
        if (t < 3) {
            int nxt = (t + 1) & 1;
            #pragma unroll
            for (int p = 0; p < 2; p++) {
                int idx = tid + p * 256;
                int m = idx >> 2, kv = (idx & 3) * 4;
                As[nxt][kv + 0][m] = ra[p].x; As[nxt][kv + 1][m] = ra[p].y;
                As[nxt][kv + 2][m] = ra[p].z; As[nxt][kv + 3][m] = ra[p].w;
            }
            #pragma unroll
            for (int qq = 0; qq < 2; qq++) {
                int idx = tid + qq * 256;
                int k = idx >> 5, nv = (idx & 31) * 4;
                *reinterpret_cast<float4*>(&Bs[nxt][k][nv]) = rb[qq];
            }
        }
        __syncthreads();
    }

    const int cbase = n0 + tn * 8;
    const int gate = cbase >> 6;
    const int d = cbase & 63;
    float wt8[8], bi8[8];
    #pragma unroll
    for (int j = 0; j < 8; j++) { wt8[j] = g_wt[cbase + j]; bi8[j] = g_bias[cbase + j]; }

    #pragma unroll
    for (int i = 0; i < 4; i++) {
        float2 u[8];
        #pragma unroll
        for (int j = 0; j < 8; j++) u[j] = unpack2(acc[i][j]);
        #pragma unroll
        for (int h = 0; h < 2; h++) {
            size_t rg = r0 + tm * 8 + 2 * i + h;
            float dy = days ? days[rg] : 0.f;
            float v[8];
            #pragma unroll
            for (int j = 0; j < 8; j++)
                v[j] = (h ? u[j].y : u[j].x) + bi8[j] + dy * wt8[j];
            if (gate == 2) {
                #pragma unroll
                for (int j = 0; j < 8; j++) v[j] = fast_tanh(v[j]);
            } else if (gate == 4) {
                #pragma unroll
                for (int j = 0; j < 8; j++) v[j] = fsoftplus(v[j]);
            } else if (gate != 5) {
                #pragma unroll
                for (int j = 0; j < 8; j++) v[j] = fsigmoid(v[j]);
            }
            float* dst = gates + ((size_t)gate * M + rg) * 64 + d;
            *reinterpret_cast<float4*>(dst)     = make_float4(v[0], v[1], v[2], v[3]);
            *reinterpret_cast<float4*>(dst + 4) = make_float4(v[4], v[5], v[6], v[7]);
        }
    }
}

// ---------------------------------------------------------------------------
// Chunk-parallel CT-LSTM scan (unchanged from R5)
// ---------------------------------------------------------------------------
__global__ __launch_bounds__(256) void scanA_kernel(const float* __restrict__ gates) {
    int t = blockIdx.x * 256 + threadIdx.x;
    int d = t & 63, rest = t >> 6;
    int b = rest & 255, ch = rest >> 8;
    const size_t S = (size_t)Mseq * 64;
    size_t base = ((size_t)(b * Lm + ch * CL)) * 64 + d;
    float c = 0.f, P = 1.f;
    #pragma unroll 5
    for (int l = 0; l < CL; l++) {
        size_t idx = base + (size_t)l * 64;
        float i_ = gates[idx];
        float f_ = gates[S + idx];
        float z_ = gates[2 * S + idx];
        c = f_ * c + i_ * z_;
        P *= f_;
    }
    g_scanA[t] = c;
    g_scanP[t] = P;
}

__global__ __launch_bounds__(256) void scanB_kernel() {
    int t = blockIdx.x * 256 + threadIdx.x;
    float c = 0.f;
    #pragma unroll
    for (int ch = 0; ch < NC; ch++) {
        int q = ch * 16384 + t;
        g_scanCin[q] = c;
        c = g_scanP[q] * c + g_scanA[q];
    }
    g_Clast[t] = c;
}

__global__ __launch_bounds__(256) void scanC_kernel(const float* __restrict__ gates,
                                                    const float* __restrict__ days) {
    int t = blockIdx.x * 256 + threadIdx.x;
    int d = t & 63, rest = t >> 6;
    int b = rest & 255, ch = rest >> 8;
    const size_t S = (size_t)Mseq * 64;
    size_t base = ((size_t)(b * Lm + ch * CL)) * 64 + d;
    const float* dptr = days + b * Lm + ch * CL;
    float c = g_scanCin[t];
    #pragma unroll 5
    for (int l = 0; l < CL; l++) {
        size_t idx = base + (size_t)l * 64;
        float i_ = gates[idx];
        float f_ = gates[S + idx];
        float z_ = gates[2 * S + idx];
        float o_ = gates[3 * S + idx];
        float dl = gates[4 * S + idx];
        float cb = gates[5 * S + idx];
        float dt = fmaxf(dptr[l], 0.f);
        c = f_ * c + i_ * z_;
        float e = __expf(-dl * dt);
        float cd = cb + (c - cb) * e;
        g_Hs[idx] = o_ * fast_tanh(cd);
    }
}

// ---------------------------------------------------------------------------
// Final CT-LSTM step at dt = 0
// ---------------------------------------------------------------------------
__global__ void final_ch_kernel() {
    int b = blockIdx.x, d = threadIdx.x;
    const int S = Bm * 64;
    int idx = b * 64 + d;
    float c = g_Gc[S + idx] * g_Clast[idx] + g_Gc[idx] * g_Gc[2 * S + idx];
    g_Hcur[idx] = g_Gc[3 * S + idx] * fast_tanh(c);
}

// ---------------------------------------------------------------------------
// Intensity MLP (unchanged from R5; Ys aliased into rows buffer)
// ---------------------------------------------------------------------------
__global__ __launch_bounds__(256) void intensity_kernel(const float* __restrict__ src, int M,
                                                        const float* __restrict__ W1,
                                                        const float* __restrict__ b1,
                                                        const float* __restrict__ W2,
                                                        const float* __restrict__ b2,
                                                        float* __restrict__ out) {
    __shared__ __align__(16) float rows[128][68];
    __shared__ __align__(16) float W1s[2048];
    __shared__ float W2s[192], b1s[32], b2s[6];
    float* Ys = &rows[0][0];
    int tid = threadIdx.x;
    size_t r0 = (size_t)blockIdx.x * 128;

    for (int i4 = tid; i4 < 512; i4 += 256)
        *reinterpret_cast<float4*>(&W1s[i4 * 4]) = reinterpret_cast<const float4*>(W1)[i4];
    if (tid < 192) W2s[tid] = W2[tid];
    if (tid < 32) b1s[tid] = b1[tid];
    if (tid < 6) b2s[tid] = b2[tid];
    #pragma unroll
    for (int p = 0; p < 8; p++) {
        int idx = tid + p * 256;
        int m = idx >> 4, dv = (idx & 15) * 4;
        *reinterpret_cast<float4*>(&rows[m][dv]) =
            *reinterpret_cast<const float4*>(src + (r0 + m) * 64 + dv);
    }
    __syncthreads();

    int tr = tid >> 3, tc = tid & 7;
    float acc[4][4];
    #pragma unroll
    for (int i = 0; i < 4; i++)
        #pragma unroll
        for (int j = 0; j < 4; j++) acc[i][j] = b1s[tc * 4 + j];
    #pragma unroll 4
    for (int k = 0; k < 64; k++) {
        float4 w = *reinterpret_cast<const float4*>(&W1s[k * 32 + tc * 4]);
        float a0 = rows[tr * 4 + 0][k];
        float a1 = rows[tr * 4 + 1][k];
        float a2 = rows[tr * 4 + 2][k];
        float a3 = rows[tr * 4 + 3][k];
        acc[0][0] = fmaf(a0, w.x, acc[0][0]); acc[0][1] = fmaf(a0, w.y, acc[0][1]);
        acc[0][2] = fmaf(a0, w.z, acc[0][2]); acc[0][3] = fmaf(a0, w.w, acc[0][3]);
        acc[1][0] = fmaf(a1, w.x, acc[1][0]); acc[1][1] = fmaf(a1, w.y, acc[1][1]);
        acc[1][2] = fmaf(a1, w.z, acc[1][2]); acc[1][3] = fmaf(a1, w.w, acc[1][3]);
        acc[2][0] = fmaf(a2, w.x, acc[2][0]); acc[2][1] = fmaf(a2, w.y, acc[2][1]);
        acc[2][2] = fmaf(a2, w.z, acc[2][2]); acc[2][3] = fmaf(a2, w.w, acc[2][3]);
        acc[3][0] = fmaf(a3, w.x, acc[3][0]); acc[3][1] = fmaf(a3, w.y, acc[3][1]);
        acc[3][2] = fmaf(a3, w.z, acc[3][2]); acc[3][3] = fmaf(a3, w.w, acc[3][3]);
    }
    __syncthreads();
    #pragma unroll
    for (int i = 0; i < 4; i++)
        #pragma unroll
        for (int j = 0; j < 4; j++)
            Ys[(tr * 4 + i) * 33 + tc * 4 + j] = fgelu(acc[i][j]);
    __syncthreads();

    if (tid < 128) {
        int row = tid;
        float o6[6];
        #pragma unroll
        for (int c = 0; c < 6; c++) o6[c] = b2s[c];
        #pragma unroll 4
        for (int k = 0; k < 32; k++) {
            float a = Ys[row * 33 + k];
            #pragma unroll
            for (int c = 0; c < 6; c++) o6[c] = fmaf(a, W2s[k * 6 + c], o6[c]);
        }
        #pragma unroll
        for (int c = 0; c < 6; c++) out[(r0 + row) * 6 + c] = fsoftplus(o6[c]);
    }
}

// ---------------------------------------------------------------------------
// TTE head (unchanged)
// ---------------------------------------------------------------------------
__global__ __launch_bounds__(256) void tte_kernel(const float* __restrict__ W1,
                                                  const float* __restrict__ b1,
                                                  const float* __restrict__ W2,
                                                  const float* __restrict__ b2,
                                                  float* __restrict__ out) {
    __shared__ float W1s[64 * 32];
    __shared__ float W2s[32];
    __shared__ float b1s[32];
    __shared__ float b2s0;
    __shared__ float rows[8][64];
    int tid = threadIdx.x;
    for (int i = tid; i < 2048; i += 256) W1s[i] = W1[i];
    if (tid < 32) { W2s[tid] = W2[tid]; b1s[tid] = b1[tid]; }
    if (tid == 0) b2s0 = b2[0];
    __syncthreads();
    int warp = tid >> 5, lane = tid & 31;
    int b = blockIdx.x * 8 + warp;
    if (b >= Bm) return;
    rows[warp][lane] = g_Hcur[b * 64 + lane];
    rows[warp][lane + 32] = g_Hcur[b * 64 + lane + 32];
    __syncwarp();
    float acc = b1s[lane];
    #pragma unroll
    for (int k = 0; k < 64; k++) acc = fmaf(rows[warp][k], W1s[k * 32 + lane], acc);
    float y = fgelu(acc);
    float p = y * W2s[lane];
    #pragma unroll
    for (int off = 16; off; off >>= 1) p += __shfl_xor_sync(0xffffffffu, p, off);
    if (lane == 0) out[b] = fsoftplus(p + b2s0);
}

// ---------------------------------------------------------------------------
// Direct head + softmax (unchanged)
// ---------------------------------------------------------------------------
__global__ __launch_bounds__(384) void direct_kernel(const float* __restrict__ cls,
                                                     const float* __restrict__ Ws1,
                                                     const float* __restrict__ bs1,
                                                     const float* __restrict__ Ws2,
                                                     const float* __restrict__ bs2,
                                                     const float* __restrict__ ci,
                                                     float* __restrict__ probs) {
    __shared__ float cls_s[4 * 768];
    __shared__ float s1[4][384];
    __shared__ float logit_s[4][6];
    int tid = threadIdx.x;
    int b0 = blockIdx.x * 4;
    for (int idx = tid; idx < 4 * 768; idx += 384)
        cls_s[idx] = cls[(size_t)b0 * 768 + idx];
    __syncthreads();
    float a0 = bs1[tid], a1 = a0, a2 = a0, a3 = a0;
    #pragma unroll 4
    for (int k = 0; k < 768; k++) {
        float w = Ws1[(size_t)k * 384 + tid];
        a0 = fmaf(cls_s[k], w, a0);
        a1 = fmaf(cls_s[768 + k], w, a1);
        a2 = fmaf(cls_s[1536 + k], w, a2);
        a3 = fmaf(cls_s[2304 + k], w, a3);
    }
    s1[0][tid] = fgelu(a0);
    s1[1][tid] = fgelu(a1);
    s1[2][tid] = fgelu(a2);
    s1[3][tid] = fgelu(a3);
    __syncthreads();
    int w = tid >> 5, lane = tid & 31;
    if (w < 6) {
        for (int g = 0; g < 4; g++) {
            float p = 0.f;
            #pragma unroll
            for (int j = lane; j < 384; j += 32) p = fmaf(s1[g][j], Ws2[(size_t)j * 6 + w], p);
            #pragma unroll
            for (int off = 16; off; off >>= 1) p += __shfl_xor_sync(0xffffffffu, p, off);
            if (lane == 0) logit_s[g][w] = p + bs2[w];
        }
    }
    __syncthreads();
    if (tid < 4) {
        int g = tid;
        float x[6], m = -1e30f;
        #pragma unroll
        for (int c = 0; c < 6; c++) {
            x[c] = logit_s[g][c] + logf(ci[(size_t)(b0 + g) * 6 + c]);
            m = fmaxf(m, x[c]);
        }
        float s = 0.f;
        #pragma unroll
        for (int c = 0; c < 6; c++) { x[c] = __expf(x[c] - m); s += x[c]; }
        float inv = __fdividef(1.f, s);
        #pragma unroll
        for (int c = 0; c < 6; c++) probs[(size_t)(b0 + g) * 6 + c] = x[c] * inv;
    }
}

// ---------------------------------------------------------------------------
// Launch
// ---------------------------------------------------------------------------
extern "C" void kernel_launch(void* const* d_in, const int* in_sizes, int n_in,
                              void* d_out, int out_size) {
    const float* cls   = (const float*)d_in[0];
    const float* ev    = (const float*)d_in[1];
    const float* days  = (const float*)d_in[2];
    const float* We    = (const float*)d_in[3];
    const float* be    = (const float*)d_in[4];
    const float* Wtime = (const float*)d_in[5];
    const float* btime = (const float*)d_in[6];
    const float* Wg    = (const float*)d_in[7];
    const float* bg    = (const float*)d_in[8];
    const float* Wi1   = (const float*)d_in[9];
    const float* bi1   = (const float*)d_in[10];
    const float* Wi2   = (const float*)d_in[11];
    const float* bi2   = (const float*)d_in[12];
    const float* Ws1   = (const float*)d_in[13];
    const float* bs1   = (const float*)d_in[14];
    const float* Ws2   = (const float*)d_in[15];
    const float* bs2   = (const float*)d_in[16];
    const float* Wq1   = (const float*)d_in[17];
    const float* bq1   = (const float*)d_in[18];
    const float* Wq2   = (const float*)d_in[19];
    const float* bq2   = (const float*)d_in[20];

    float* out = (float*)d_out;
    float* out_probs = out;
    float* out_tte   = out + 1536;
    float* out_ci    = out + 1536 + 256;
    float* out_hist  = out + 1536 + 256 + 1536;

    float *pE, *pG, *pEc, *pGc, *pHs, *pHcur;
    unsigned *pWeHi, *pWeLo;
    cudaGetSymbolAddress((void**)&pE, g_E);
    cudaGetSymbolAddress((void**)&pG, g_G);
    cudaGetSymbolAddress((void**)&pEc, g_Ec);
    cudaGetSymbolAddress((void**)&pGc, g_Gc);
    cudaGetSymbolAddress((void**)&pHs, g_Hs);
    cudaGetSymbolAddress((void**)&pHcur, g_Hcur);
    cudaGetSymbolAddress((void**)&pWeHi, g_WeHi);
    cudaGetSymbolAddress((void**)&pWeLo, g_WeLo);

    setup_kernel<<<1, 384>>>(Wtime, btime, Wg, bg);
    split_we_kernel<<<96, 256>>>(We);

    gemm1_mma<<<Mseq / 128, 256>>>(ev, pWeHi, pWeLo, be, pE);
    gemm1_mma<<<Bm / 128, 256>>>(cls, pWeHi, pWeLo, be, pEc);

    gemm2_kernel<<<dim3(Mseq / 128, 3), 256>>>(pE, Wg, days, pG, Mseq);
    gemm2_kernel<<<dim3(Bm / 128, 3), 256>>>(pEc, Wg, nullptr, pGc, Bm);

    scanA_kernel<<<(Bm * Dm * NC) / 256, 256>>>(pG);
    scanB_kernel<<<(Bm * Dm) / 256, 256>>>();
    scanC_kernel<<<(Bm * Dm * NC) / 256, 256>>>(pG, days);
    final_ch_kernel<<<Bm, 64>>>();

    intensity_kernel<<<Mseq / 128, 256>>>(pHs, Mseq, Wi1, bi1, Wi2, bi2, out_hist);
    intensity_kernel<<<Bm / 128, 256>>>(pHcur, Bm, Wi1, bi1, Wi2, bi2, out_ci);
    tte_kernel<<<Bm / 8, 256>>>(Wq1, bq1, Wq2, bq2, out_tte);
    direct_kernel<<<Bm / 4, 384>>>(cls, Ws1, bs1, Ws2, bs2, out_ci, out_probs);
}

// round 9
// speedup vs baseline: 1.1253x; 1.1253x over previous
#include <cuda_runtime.h>
#include <cuda_bf16.h>
#include <math.h>
#include <stdint.h>

// ---------------------------------------------------------------------------
// Problem constants
// ---------------------------------------------------------------------------
#define Bm 256
#define Lm 200
#define Hm 768
#define Dm 64
#define NS 6
#define Mseq (Bm * Lm)          // 51200
#define NC 8                    // scan chunks
#define CL 25                   // Lm / NC
#define NEVB (Mseq / 128)       // 400 blocks for the sequence rows

typedef unsigned long long ull;

// ---------------------------------------------------------------------------
// Device scratch (static globals — no allocation allowed)
// ---------------------------------------------------------------------------
__device__ float g_E[(size_t)Mseq * Dm];            // E = ev@We+be
__device__ float g_G[(size_t)6 * Mseq * Dm];        // activated gates (gate, row, d)
__device__ float g_Hs[(size_t)Mseq * Dm];           // hidden states
__device__ float g_Ec[Bm * Dm];
__device__ float g_Gc[6 * Bm * Dm];
__device__ float g_Clast[Bm * Dm];
__device__ float g_Hcur[Bm * Dm];
__device__ float g_wt[384];                          // Wtime @ Wg_bot
__device__ float g_bias[384];                        // btime @ Wg_bot + bg
__device__ float g_scanP[Bm * Dm * NC];              // chunk prod(f)
__device__ float g_scanA[Bm * Dm * NC];              // chunk affine term
__device__ float g_scanCin[Bm * Dm * NC];            // chunk entry carry
__device__ unsigned g_WeHi[384 * 64];                // We split: packed bf16x2 (k pairs)
__device__ unsigned g_WeLo[384 * 64];

// ---------------------------------------------------------------------------
// Math helpers
// ---------------------------------------------------------------------------
__device__ __forceinline__ float fast_tanh(float x) {
    float y;
    asm("tanh.approx.f32 %0, %1;" : "=f"(y) : "f"(x));
    return y;
}
__device__ __forceinline__ float fsigmoid(float x) {
    return __fdividef(1.0f, 1.0f + __expf(-x));
}
__device__ __forceinline__ float fsoftplus(float x) {
    return fmaxf(x, 0.0f) + log1pf(__expf(-fabsf(x)));
}
__device__ __forceinline__ float fgelu(float x) {
    return 0.5f * x * (1.0f + erff(x * 0.70710678118654752f));
}
// pack two f32 -> bf16x2 (lo = first element in lower 16 bits)
__device__ __forceinline__ unsigned bfpair(float lo, float hi) {
    unsigned r;
    asm("cvt.rn.bf16x2.f32 %0, %1, %2;" : "=r"(r) : "f"(hi), "f"(lo));
    return r;
}
// split a float2 (consecutive-k pair) into hi/lo bf16x2 regs
__device__ __forceinline__ void split2(float2 e, unsigned& h, unsigned& l) {
    unsigned hp = bfpair(e.x, e.y);
    float h0 = __uint_as_float(hp << 16);
    float h1 = __uint_as_float(hp & 0xFFFF0000u);
    h = hp;
    l = bfpair(e.x - h0, e.y - h1);
}
__device__ __forceinline__ void mma_bf16(float* c, const unsigned* a, unsigned b0, unsigned b1) {
    asm volatile(
        "mma.sync.aligned.m16n8k16.row.col.f32.bf16.bf16.f32 "
        "{%0,%1,%2,%3}, {%4,%5,%6,%7}, {%8,%9}, {%0,%1,%2,%3};"
        : "+f"(c[0]), "+f"(c[1]), "+f"(c[2]), "+f"(c[3])
        : "r"(a[0]), "r"(a[1]), "r"(a[2]), "r"(a[3]), "r"(b0), "r"(b1));
}

// ---------------------------------------------------------------------------
// Setup: wt[c] = sum_d Wtime[d]*Wg[64+d,c]; bias[c] = sum_d btime[d]*Wg[64+d,c] + bg[c]
// ---------------------------------------------------------------------------
__global__ void setup_kernel(const float* __restrict__ Wtime, const float* __restrict__ btime,
                             const float* __restrict__ Wg, const float* __restrict__ bg) {
    int c = threadIdx.x;   // 384 threads
    float s1 = 0.f, s2 = 0.f;
    #pragma unroll 8
    for (int d = 0; d < 64; d++) {
        float w = Wg[(size_t)(64 + d) * 384 + c];
        s1 += Wtime[d] * w;
        s2 += btime[d] * w;
    }
    g_wt[c] = s1;
    g_bias[c] = s2 + bg[c];
}

// Split We[768,64] into packed bf16x2 hi/lo planes: index t = j*64+n, j=k/2.
__global__ void split_we_kernel(const float* __restrict__ We) {
    int t = blockIdx.x * 256 + threadIdx.x;   // 0..24575
    if (t >= 384 * 64) return;
    int j = t >> 6, n = t & 63;
    float e0 = We[(size_t)(2 * j) * 64 + n];
    float e1 = We[(size_t)(2 * j + 1) * 64 + n];
    unsigned hp = bfpair(e0, e1);
    float h0 = __uint_as_float(hp << 16);
    float h1 = __uint_as_float(hp & 0xFFFF0000u);
    g_WeHi[t] = hp;
    g_WeLo[t] = bfpair(e0 - h0, e1 - h1);
}

// ---------------------------------------------------------------------------
// GEMM1 via bf16-split tensor-core mma. MERGED: blocks [0,NEVB) process the
// event rows (Aev -> Cev); blocks [NEVB, NEVB+2) process cls (Acls -> Ccls).
// The 2 cls blocks ride the same wave instead of a serial grid=2 launch
// (which measured 58.7us of near-idle GPU in R8).
// ---------------------------------------------------------------------------
__global__ __launch_bounds__(256) void gemm1_mma(const float* __restrict__ Aev,
                                                 const float* __restrict__ Acls,
                                                 const unsigned* __restrict__ BHi,
                                                 const unsigned* __restrict__ BLo,
                                                 const float* __restrict__ be,
                                                 float* __restrict__ Cev,
                                                 float* __restrict__ Ccls) {
    __shared__ __align__(16) float As[2][128][20];        // [m][k] + pad (80B rows)
    __shared__ __align__(16) unsigned BsH[2][8][64];      // [j][n] packed bf16x2
    __shared__ __align__(16) unsigned BsL[2][8][64];
    const int tid = threadIdx.x;
    const int wid = tid >> 5, lane = tid & 31;
    const int warpR = wid >> 1;          // 0..3 : rows warpR*32
    const int warpC = wid & 1;           // 0..1 : cols warpC*32
    const int q = lane & 3, rr = lane >> 2;

    const float* A;
    float* C;
    size_t r0;
    if (blockIdx.x < NEVB) {
        A = Aev;  C = Cev;  r0 = (size_t)blockIdx.x * 128;
    } else {
        A = Acls; C = Ccls; r0 = (size_t)(blockIdx.x - NEVB) * 128;
    }

    float acc[2][4][4];
    #pragma unroll
    for (int mt = 0; mt < 2; mt++)
        #pragma unroll
        for (int nt = 0; nt < 4; nt++)
            #pragma unroll
            for (int i = 0; i < 4; i++) acc[mt][nt][i] = 0.f;

    // tile 0 loads
    {
        #pragma unroll
        for (int p = 0; p < 2; p++) {
            int idx = tid + p * 256;
            int m = idx >> 2, kv = (idx & 3) * 4;
            *reinterpret_cast<float4*>(&As[0][m][kv]) =
                *reinterpret_cast<const float4*>(A + (r0 + m) * 768 + kv);
        }
        *reinterpret_cast<uint2*>(&BsH[0][0][0] + tid * 2) =
            *reinterpret_cast<const uint2*>(BHi + tid * 2);
        *reinterpret_cast<uint2*>(&BsL[0][0][0] + tid * 2) =
            *reinterpret_cast<const uint2*>(BLo + tid * 2);
    }
    __syncthreads();

    #pragma unroll 2
    for (int t = 0; t < 48; t++) {
        int cur = t & 1;
        // prefetch next tile into other buffer
        if (t < 47) {
            int nxt = cur ^ 1;
            int k0 = (t + 1) * 16;
            #pragma unroll
            for (int p = 0; p < 2; p++) {
                int idx = tid + p * 256;
                int m = idx >> 2, kv = (idx & 3) * 4;
                *reinterpret_cast<float4*>(&As[nxt][m][kv]) =
                    *reinterpret_cast<const float4*>(A + (r0 + m) * 768 + k0 + kv);
            }
            size_t jb = (size_t)(t + 1) * 8 * 64;
            *reinterpret_cast<uint2*>(&BsH[nxt][0][0] + tid * 2) =
                *reinterpret_cast<const uint2*>(BHi + jb + tid * 2);
            *reinterpret_cast<uint2*>(&BsL[nxt][0][0] + tid * 2) =
                *reinterpret_cast<const uint2*>(BLo + jb + tid * 2);
        }

        // A fragments (hi/lo) for 2 m-tiles
        unsigned aH[2][4], aL[2][4];
        #pragma unroll
        for (int mt = 0; mt < 2; mt++) {
            int row = warpR * 32 + mt * 16 + rr;
            #pragma unroll
            for (int kk = 0; kk < 2; kk++) {
                float2 e0 = *reinterpret_cast<const float2*>(&As[cur][row][2 * q + 8 * kk]);
                float2 e1 = *reinterpret_cast<const float2*>(&As[cur][row + 8][2 * q + 8 * kk]);
                split2(e0, aH[mt][2 * kk + 0], aL[mt][2 * kk + 0]);
                split2(e1, aH[mt][2 * kk + 1], aL[mt][2 * kk + 1]);
            }
        }
        // per n-tile B fragments + 3-split mma
        #pragma unroll
        for (int nt = 0; nt < 4; nt++) {
            int c = warpC * 32 + nt * 8 + rr;
            unsigned bH0 = BsH[cur][q][c],     bH1 = BsH[cur][q + 4][c];
            unsigned bL0 = BsL[cur][q][c],     bL1 = BsL[cur][q + 4][c];
            #pragma unroll
            for (int mt = 0; mt < 2; mt++) {
                mma_bf16(acc[mt][nt], aH[mt], bH0, bH1);
                mma_bf16(acc[mt][nt], aH[mt], bL0, bL1);
                mma_bf16(acc[mt][nt], aL[mt], bH0, bH1);
            }
        }
        __syncthreads();
    }

    // epilogue: + be, direct float2 stores
    #pragma unroll
    for (int nt = 0; nt < 4; nt++) {
        int col = warpC * 32 + nt * 8 + 2 * q;
        float b0 = be[col], b1 = be[col + 1];
        #pragma unroll
        for (int mt = 0; mt < 2; mt++) {
            size_t row = r0 + warpR * 32 + mt * 16 + rr;
            *reinterpret_cast<float2*>(C + row * 64 + col) =
                make_float2(acc[mt][nt][0] + b0, acc[mt][nt][1] + b1);
            *reinterpret_cast<float2*>(C + (row + 8) * 64 + col) =
                make_float2(acc[mt][nt][2] + b0, acc[mt][nt][3] + b1);
        }
    }
}

// ---------------------------------------------------------------------------
// GEMM2: gates = act( E[M,64] @ Wg_top[64,384] + days[row]*wt + bias )
// MERGED: blocks.x in [0,NEVB) -> event rows (g_E -> g_G, with days);
// blocks.x in [NEVB,NEVB+2) -> cls rows (g_Ec -> g_Gc, days=0).
// ---------------------------------------------------------------------------
__device__ __forceinline__ void fma2(ull& d, ull a, ull b) {
    asm("fma.rn.f32x2 %0, %1, %2, %0;" : "+l"(d) : "l"(a), "l"(b));
}
__device__ __forceinline__ ull pack2(float x, float y) {
    ull r;
    asm("mov.b64 %0, {%1, %2};" : "=l"(r) : "f"(x), "f"(y));
    return r;
}
__device__ __forceinline__ float2 unpack2(ull v) {
    float2 r;
    asm("mov.b64 {%0, %1}, %2;" : "=f"(r.x), "=f"(r.y) : "l"(v));
    return r;
}

__global__ __launch_bounds__(256) void gemm2_kernel(const float* __restrict__ Eev,
                                                    const float* __restrict__ Ecls,
                                                    const float* __restrict__ Wg,
                                                    const float* __restrict__ days_in,
                                                    float* __restrict__ Gev,
                                                    float* __restrict__ Gcls) {
    __shared__ __align__(16) float As[2][16][132];
    __shared__ __align__(16) float Bs[2][16][128];
    const int tid = threadIdx.x;
    const int n0 = blockIdx.y * 128;
    const int tm = tid >> 4;
    const int tn = tid & 15;

    const float* E;
    const float* days;
    float* gates;
    int M;
    size_t r0;
    if (blockIdx.x < NEVB) {
        E = Eev;  days = days_in; gates = Gev;  M = Mseq;
        r0 = (size_t)blockIdx.x * 128;
    } else {
        E = Ecls; days = nullptr; gates = Gcls; M = Bm;
        r0 = (size_t)(blockIdx.x - NEVB) * 128;
    }

    ull acc[4][8];
    #pragma unroll
    for (int i = 0; i < 4; i++)
        #pragma unroll
        for (int j = 0; j < 8; j++) acc[i][j] = 0ull;

    float4 ra[2], rb[2];
    #pragma unroll
    for (int p = 0; p < 2; p++) {
        int idx = tid + p * 256;
        int m = idx >> 2, kv = (idx & 3) * 4;
        ra[p] = *reinterpret_cast<const float4*>(E + (r0 + m) * 64 + kv);
    }
    #pragma unroll
    for (int qq = 0; qq < 2; qq++) {
        int idx = tid + qq * 256;
        int k = idx >> 5, nv = (idx & 31) * 4;
        rb[qq] = *reinterpret_cast<const float4*>(Wg + (size_t)k * 384 + n0 + nv);
    }
    #pragma unroll
    for (int p = 0; p < 2; p++) {
        int idx = tid + p * 256;
        int m = idx >> 2, kv = (idx & 3) * 4;
        As[0][kv + 0][m] = ra[p].x; As[0][kv + 1][m] = ra[p].y;
        As[0][kv + 2][m] = ra[p].z; As[0][kv + 3][m] = ra[p].w;
    }
    #pragma unroll
    for (int qq = 0; qq < 2; qq++) {
        int idx = tid + qq * 256;
        int k = idx >> 5, nv = (idx & 31) * 4;
        *reinterpret_cast<float4*>(&Bs[0][k][nv]) = rb[qq];
    }
    __syncthreads();

    #pragma unroll 2
    for (int t = 0; t < 4; t++) {
        int cur = t & 1;
        if (t < 3) {
            int k0 = (t + 1) * 16;
            #pragma unroll
            for (int p = 0; p < 2; p++) {
                int idx = tid + p * 256;
                int m = idx >> 2, kv = (idx & 3) * 4;
                ra[p] = *reinterpret_cast<const float4*>(E + (r0 + m) * 64 + k0 + kv);
            }
            #pragma unroll
            for (int qq = 0; qq < 2; qq++) {
                int idx = tid + qq * 256;
                int k = idx >> 5, nv = (idx & 31) * 4;
                rb[qq] = *reinterpret_cast<const float4*>(Wg + (size_t)(k0 + k) * 384 + n0 + nv);
            }
        }
        #pragma unroll
        for (int kk = 0; kk < 16; kk++) {
            const ull* pa = reinterpret_cast<const ull*>(&As[cur][kk][tm * 8]);
            ull a0 = pa[0], a1 = pa[1], a2 = pa[2], a3 = pa[3];
            float4 bA = *reinterpret_cast<const float4*>(&Bs[cur][kk][tn * 8]);
            float4 bB = *reinterpret_cast<const float4*>(&Bs[cur][kk][tn * 8 + 4]);
            ull bp[8];
            bp[0] = pack2(bA.x, bA.x); bp[1] = pack2(bA.y, bA.y);
            bp[2] = pack2(bA.z, bA.z); bp[3] = pack2(bA.w, bA.w);
            bp[4] = pack2(bB.x, bB.x); bp[5] = pack2(bB.y, bB.y);
            bp[6] = pack2(bB.z, bB.z); bp[7] = pack2(bB.w, bB.w);
            #pragma unroll
            for (int j = 0; j < 8; j++) {
                fma2(acc[0][j], a0, bp[j]);
                fma2(acc[1][j], a1, bp[j]);
                fma2(acc[2][j], a2, bp[j]);
                fma2(acc[3][j], a3, bp[j]);
            }
        }
        if (t < 3) {
            int nxt = (t + 1) & 1;
            #pragma unroll
            for (int p = 0; p < 2; p++) {
                int idx = tid + p * 256;
                int m = idx >> 2, kv = (idx & 3) * 4;
                As[nxt][kv + 0][m] = ra[p].x; As[nxt][kv + 1][m] = ra[p].y;
                As[nxt][kv + 2][m] = ra[p].z; As[nxt][kv + 3][m] = ra[p].w;
            }
            #pragma unroll
            for (int qq = 0; qq < 2; qq++) {
                int idx = tid + qq * 256;
                int k = idx >> 5, nv = (idx & 31) * 4;
                *reinterpret_cast<float4*>(&Bs[nxt][k][nv]) = rb[qq];
            }
        }
        __syncthreads();
    }

    const int cbase = n0 + tn * 8;
    const int gate = cbase >> 6;
    const int d = cbase & 63;
    float wt8[8], bi8[8];
    #pragma unroll
    for (int j = 0; j < 8; j++) { wt8[j] = g_wt[cbase + j]; bi8[j] = g_bias[cbase + j]; }

    #pragma unroll
    for (int i = 0; i < 4; i++) {
        float2 u[8];
        #pragma unroll
        for (int j = 0; j < 8; j++) u[j] = unpack2(acc[i][j]);
        #pragma unroll
        for (int h = 0; h < 2; h++) {
            size_t rg = r0 + tm * 8 + 2 * i + h;
            float dy = days ? days[rg] : 0.f;
            float v[8];
            #pragma unroll
            for (int j = 0; j < 8; j++)
                v[j] = (h ? u[j].y : u[j].x) + bi8[j] + dy * wt8[j];
            if (gate == 2) {
                #pragma unroll
                for (int j = 0; j < 8; j++) v[j] = fast_tanh(v[j]);
            } else if (gate == 4) {
                #pragma unroll
                for (int j = 0; j < 8; j++) v[j] = fsoftplus(v[j]);
            } else if (gate != 5) {
                #pragma unroll
                for (int j = 0; j < 8; j++) v[j] = fsigmoid(v[j]);
            }
            float* dst = gates + ((size_t)gate * M + rg) * 64 + d;
            *reinterpret_cast<float4*>(dst)     = make_float4(v[0], v[1], v[2], v[3]);
            *reinterpret_cast<float4*>(dst + 4) = make_float4(v[4], v[5], v[6], v[7]);
        }
    }
}

// ---------------------------------------------------------------------------
// Chunk-parallel CT-LSTM scan (unchanged)
// ---------------------------------------------------------------------------
__global__ __launch_bounds__(256) void scanA_kernel(const float* __restrict__ gates) {
    int t = blockIdx.x * 256 + threadIdx.x;
    int d = t & 63, rest = t >> 6;
    int b = rest & 255, ch = rest >> 8;
    const size_t S = (size_t)Mseq * 64;
    size_t base = ((size_t)(b * Lm + ch * CL)) * 64 + d;
    float c = 0.f, P = 1.f;
    #pragma unroll 5
    for (int l = 0; l < CL; l++) {
        size_t idx = base + (size_t)l * 64;
        float i_ = gates[idx];
        float f_ = gates[S + idx];
        float z_ = gates[2 * S + idx];
        c = f_ * c + i_ * z_;
        P *= f_;
    }
    g_scanA[t] = c;
    g_scanP[t] = P;
}

__global__ __launch_bounds__(256) void scanB_kernel() {
    int t = blockIdx.x * 256 + threadIdx.x;
    float c = 0.f;
    #pragma unroll
    for (int ch = 0; ch < NC; ch++) {
        int q = ch * 16384 + t;
        g_scanCin[q] = c;
        c = g_scanP[q] * c + g_scanA[q];
    }
    g_Clast[t] = c;
}

__global__ __launch_bounds__(256) void scanC_kernel(const float* __restrict__ gates,
                                                    const float* __restrict__ days) {
    int t = blockIdx.x * 256 + threadIdx.x;
    int d = t & 63, rest = t >> 6;
    int b = rest & 255, ch = rest >> 8;
    const size_t S = (size_t)Mseq * 64;
    size_t base = ((size_t)(b * Lm + ch * CL)) * 64 + d;
    const float* dptr = days + b * Lm + ch * CL;
    float c = g_scanCin[t];
    #pragma unroll 5
    for (int l = 0; l < CL; l++) {
        size_t idx = base + (size_t)l * 64;
        float i_ = gates[idx];
        float f_ = gates[S + idx];
        float z_ = gates[2 * S + idx];
        float o_ = gates[3 * S + idx];
        float dl = gates[4 * S + idx];
        float cb = gates[5 * S + idx];
        float dt = fmaxf(dptr[l], 0.f);
        c = f_ * c + i_ * z_;
        float e = __expf(-dl * dt);
        float cd = cb + (c - cb) * e;
        g_Hs[idx] = o_ * fast_tanh(cd);
    }
}

// ---------------------------------------------------------------------------
// Final CT-LSTM step at dt = 0
// ---------------------------------------------------------------------------
__global__ void final_ch_kernel() {
    int b = blockIdx.x, d = threadIdx.x;
    const int S = Bm * 64;
    int idx = b * 64 + d;
    float c = g_Gc[S + idx] * g_Clast[idx] + g_Gc[idx] * g_Gc[2 * S + idx];
    g_Hcur[idx] = g_Gc[3 * S + idx] * fast_tanh(c);
}

// ---------------------------------------------------------------------------
// Intensity MLP (unchanged; Ys aliased into rows buffer)
// ---------------------------------------------------------------------------
__global__ __launch_bounds__(256) void intensity_kernel(const float* __restrict__ src, int M,
                                                        const float* __restrict__ W1,
                                                        const float* __restrict__ b1,
                                                        const float* __restrict__ W2,
                                                        const float* __restrict__ b2,
                                                        float* __restrict__ out) {
    __shared__ __align__(16) float rows[128][68];
    __shared__ __align__(16) float W1s[2048];
    __shared__ float W2s[192], b1s[32], b2s[6];
    float* Ys = &rows[0][0];
    int tid = threadIdx.x;
    size_t r0 = (size_t)blockIdx.x * 128;

    for (int i4 = tid; i4 < 512; i4 += 256)
        *reinterpret_cast<float4*>(&W1s[i4 * 4]) = reinterpret_cast<const float4*>(W1)[i4];
    if (tid < 192) W2s[tid] = W2[tid];
    if (tid < 32) b1s[tid] = b1[tid];
    if (tid < 6) b2s[tid] = b2[tid];
    #pragma unroll
    for (int p = 0; p < 8; p++) {
        int idx = tid + p * 256;
        int m = idx >> 4, dv = (idx & 15) * 4;
        *reinterpret_cast<float4*>(&rows[m][dv]) =
            *reinterpret_cast<const float4*>(src + (r0 + m) * 64 + dv);
    }
    __syncthreads();

    int tr = tid >> 3, tc = tid & 7;
    float acc[4][4];
    #pragma unroll
    for (int i = 0; i < 4; i++)
        #pragma unroll
        for (int j = 0; j < 4; j++) acc[i][j] = b1s[tc * 4 + j];
    #pragma unroll 4
    for (int k = 0; k < 64; k++) {
        float4 w = *reinterpret_cast<const float4*>(&W1s[k * 32 + tc * 4]);
        float a0 = rows[tr * 4 + 0][k];
        float a1 = rows[tr * 4 + 1][k];
        float a2 = rows[tr * 4 + 2][k];
        float a3 = rows[tr * 4 + 3][k];
        acc[0][0] = fmaf(a0, w.x, acc[0][0]); acc[0][1] = fmaf(a0, w.y, acc[0][1]);
        acc[0][2] = fmaf(a0, w.z, acc[0][2]); acc[0][3] = fmaf(a0, w.w, acc[0][3]);
        acc[1][0] = fmaf(a1, w.x, acc[1][0]); acc[1][1] = fmaf(a1, w.y, acc[1][1]);
        acc[1][2] = fmaf(a1, w.z, acc[1][2]); acc[1][3] = fmaf(a1, w.w, acc[1][3]);
        acc[2][0] = fmaf(a2, w.x, acc[2][0]); acc[2][1] = fmaf(a2, w.y, acc[2][1]);
        acc[2][2] = fmaf(a2, w.z, acc[2][2]); acc[2][3] = fmaf(a2, w.w, acc[2][3]);
        acc[3][0] = fmaf(a3, w.x, acc[3][0]); acc[3][1] = fmaf(a3, w.y, acc[3][1]);
        acc[3][2] = fmaf(a3, w.z, acc[3][2]); acc[3][3] = fmaf(a3, w.w, acc[3][3]);
    }
    __syncthreads();
    #pragma unroll
    for (int i = 0; i < 4; i++)
        #pragma unroll
        for (int j = 0; j < 4; j++)
            Ys[(tr * 4 + i) * 33 + tc * 4 + j] = fgelu(acc[i][j]);
    __syncthreads();

    if (tid < 128) {
        int row = tid;
        float o6[6];
        #pragma unroll
        for (int c = 0; c < 6; c++) o6[c] = b2s[c];
        #pragma unroll 4
        for (int k = 0; k < 32; k++) {
            float a = Ys[row * 33 + k];
            #pragma unroll
            for (int c = 0; c < 6; c++) o6[c] = fmaf(a, W2s[k * 6 + c], o6[c]);
        }
        #pragma unroll
        for (int c = 0; c < 6; c++) out[(r0 + row) * 6 + c] = fsoftplus(o6[c]);
    }
}

// ---------------------------------------------------------------------------
// TTE head (unchanged)
// ---------------------------------------------------------------------------
__global__ __launch_bounds__(256) void tte_kernel(const float* __restrict__ W1,
                                                  const float* __restrict__ b1,
                                                  const float* __restrict__ W2,
                                                  const float* __restrict__ b2,
                                                  float* __restrict__ out) {
    __shared__ float W1s[64 * 32];
    __shared__ float W2s[32];
    __shared__ float b1s[32];
    __shared__ float b2s0;
    __shared__ float rows[8][64];
    int tid = threadIdx.x;
    for (int i = tid; i < 2048; i += 256) W1s[i] = W1[i];
    if (tid < 32) { W2s[tid] = W2[tid]; b1s[tid] = b1[tid]; }
    if (tid == 0) b2s0 = b2[0];
    __syncthreads();
    int warp = tid >> 5, lane = tid & 31;
    int b = blockIdx.x * 8 + warp;
    if (b >= Bm) return;
    rows[warp][lane] = g_Hcur[b * 64 + lane];
    rows[warp][lane + 32] = g_Hcur[b * 64 + lane + 32];
    __syncwarp();
    float acc = b1s[lane];
    #pragma unroll
    for (int k = 0; k < 64; k++) acc = fmaf(rows[warp][k], W1s[k * 32 + lane], acc);
    float y = fgelu(acc);
    float p = y * W2s[lane];
    #pragma unroll
    for (int off = 16; off; off >>= 1) p += __shfl_xor_sync(0xffffffffu, p, off);
    if (lane == 0) out[b] = fsoftplus(p + b2s0);
}

// ---------------------------------------------------------------------------
// Direct head + softmax (unchanged)
// ---------------------------------------------------------------------------
__global__ __launch_bounds__(384) void direct_kernel(const float* __restrict__ cls,
                                                     const float* __restrict__ Ws1,
                                                     const float* __restrict__ bs1,
                                                     const float* __restrict__ Ws2,
                                                     const float* __restrict__ bs2,
                                                     const float* __restrict__ ci,
                                                     float* __restrict__ probs) {
    __shared__ float cls_s[4 * 768];
    __shared__ float s1[4][384];
    __shared__ float logit_s[4][6];
    int tid = threadIdx.x;
    int b0 = blockIdx.x * 4;
    for (int idx = tid; idx < 4 * 768; idx += 384)
        cls_s[idx] = cls[(size_t)b0 * 768 + idx];
    __syncthreads();
    float a0 = bs1[tid], a1 = a0, a2 = a0, a3 = a0;
    #pragma unroll 4
    for (int k = 0; k < 768; k++) {
        float w = Ws1[(size_t)k * 384 + tid];
        a0 = fmaf(cls_s[k], w, a0);
        a1 = fmaf(cls_s[768 + k], w, a1);
        a2 = fmaf(cls_s[1536 + k], w, a2);
        a3 = fmaf(cls_s[2304 + k], w, a3);
    }
    s1[0][tid] = fgelu(a0);
    s1[1][tid] = fgelu(a1);
    s1[2][tid] = fgelu(a2);
    s1[3][tid] = fgelu(a3);
    __syncthreads();
    int w = tid >> 5, lane = tid & 31;
    if (w < 6) {
        for (int g = 0; g < 4; g++) {
            float p = 0.f;
            #pragma unroll
            for (int j = lane; j < 384; j += 32) p = fmaf(s1[g][j], Ws2[(size_t)j * 6 + w], p);
            #pragma unroll
            for (int off = 16; off; off >>= 1) p += __shfl_xor_sync(0xffffffffu, p, off);
            if (lane == 0) logit_s[g][w] = p + bs2[w];
        }
    }
    __syncthreads();
    if (tid < 4) {
        int g = tid;
        float x[6], m = -1e30f;
        #pragma unroll
        for (int c = 0; c < 6; c++) {
            x[c] = logit_s[g][c] + logf(ci[(size_t)(b0 + g) * 6 + c]);
            m = fmaxf(m, x[c]);
        }
        float s = 0.f;
        #pragma unroll
        for (int c = 0; c < 6; c++) { x[c] = __expf(x[c] - m); s += x[c]; }
        float inv = __fdividef(1.f, s);
        #pragma unroll
        for (int c = 0; c < 6; c++) probs[(size_t)(b0 + g) * 6 + c] = x[c] * inv;
    }
}

// ---------------------------------------------------------------------------
// Launch
// ---------------------------------------------------------------------------
extern "C" void kernel_launch(void* const* d_in, const int* in_sizes, int n_in,
                              void* d_out, int out_size) {
    const float* cls   = (const float*)d_in[0];
    const float* ev    = (const float*)d_in[1];
    const float* days  = (const float*)d_in[2];
    const float* We    = (const float*)d_in[3];
    const float* be    = (const float*)d_in[4];
    const float* Wtime = (const float*)d_in[5];
    const float* btime = (const float*)d_in[6];
    const float* Wg    = (const float*)d_in[7];
    const float* bg    = (const float*)d_in[8];
    const float* Wi1   = (const float*)d_in[9];
    const float* bi1   = (const float*)d_in[10];
    const float* Wi2   = (const float*)d_in[11];
    const float* bi2   = (const float*)d_in[12];
    const float* Ws1   = (const float*)d_in[13];
    const float* bs1   = (const float*)d_in[14];
    const float* Ws2   = (const float*)d_in[15];
    const float* bs2   = (const float*)d_in[16];
    const float* Wq1   = (const float*)d_in[17];
    const float* bq1   = (const float*)d_in[18];
    const float* Wq2   = (const float*)d_in[19];
    const float* bq2   = (const float*)d_in[20];

    float* out = (float*)d_out;
    float* out_probs = out;
    float* out_tte   = out + 1536;
    float* out_ci    = out + 1536 + 256;
    float* out_hist  = out + 1536 + 256 + 1536;

    float *pE, *pG, *pEc, *pGc, *pHs, *pHcur;
    unsigned *pWeHi, *pWeLo;
    cudaGetSymbolAddress((void**)&pE, g_E);
    cudaGetSymbolAddress((void**)&pG, g_G);
    cudaGetSymbolAddress((void**)&pEc, g_Ec);
    cudaGetSymbolAddress((void**)&pGc, g_Gc);
    cudaGetSymbolAddress((void**)&pHs, g_Hs);
    cudaGetSymbolAddress((void**)&pHcur, g_Hcur);
    cudaGetSymbolAddress((void**)&pWeHi, g_WeHi);
    cudaGetSymbolAddress((void**)&pWeLo, g_WeLo);

    setup_kernel<<<1, 384>>>(Wtime, btime, Wg, bg);
    split_we_kernel<<<96, 256>>>(We);

    // Merged big+cls launches (cls = 2 extra blocks riding the same wave)
    gemm1_mma<<<NEVB + 2, 256>>>(ev, cls, pWeHi, pWeLo, be, pE, pEc);
    gemm2_kernel<<<dim3(NEVB + 2, 3), 256>>>(pE, pEc, Wg, days, pG, pGc);

    scanA_kernel<<<(Bm * Dm * NC) / 256, 256>>>(pG);
    scanB_kernel<<<(Bm * Dm) / 256, 256>>>();
    scanC_kernel<<<(Bm * Dm * NC) / 256, 256>>>(pG, days);
    final_ch_kernel<<<Bm, 64>>>();

    intensity_kernel<<<Mseq / 128, 256>>>(pHs, Mseq, Wi1, bi1, Wi2, bi2, out_hist);
    intensity_kernel<<<Bm / 128, 256>>>(pHcur, Bm, Wi1, bi1, Wi2, bi2, out_ci);
    tte_kernel<<<Bm / 8, 256>>>(Wq1, bq1, Wq2, bq2, out_tte);
    direct_kernel<<<Bm / 4, 384>>>(cls, Ws1, bs1, Ws2, bs2, out_ci, out_probs);
}

// round 10
// speedup vs baseline: 1.2393x; 1.1012x over previous
#include <cuda_runtime.h>
#include <cuda_bf16.h>
#include <math.h>
#include <stdint.h>

// ---------------------------------------------------------------------------
// Problem constants
// ---------------------------------------------------------------------------
#define Bm 256
#define Lm 200
#define Hm 768
#define Dm 64
#define NS 6
#define Mseq (Bm * Lm)          // 51200
#define NC 8                    // scan chunks
#define CL 25                   // Lm / NC
#define NEVB (Mseq / 128)       // 400 blocks for the sequence rows

typedef unsigned long long ull;

// ---------------------------------------------------------------------------
// Device scratch (static globals — no allocation allowed)
// ---------------------------------------------------------------------------
__device__ float g_E[(size_t)Mseq * Dm];            // E = ev@We+be
__device__ float g_G[(size_t)6 * Mseq * Dm];        // activated gates (gate, row, d)
__device__ float g_Hs[(size_t)Mseq * Dm];           // hidden states
__device__ float g_Ec[Bm * Dm];
__device__ float g_Gc[6 * Bm * Dm];
__device__ float g_Clast[Bm * Dm];
__device__ float g_Hcur[Bm * Dm];
__device__ float g_wt[384];                          // Wtime @ Wg_bot
__device__ float g_bias[384];                        // btime @ Wg_bot + bg
__device__ float g_scanP[Bm * Dm * NC];              // chunk prod(f)
__device__ float g_scanA[Bm * Dm * NC];              // chunk affine term
__device__ float g_scanCin[Bm * Dm * NC];            // chunk entry carry
__device__ unsigned g_WeHi[384 * 64];                // We split: packed bf16x2 (k pairs)
__device__ unsigned g_WeLo[384 * 64];
__device__ unsigned g_WgHi[32 * 384];                // Wg_top split: [kpair][n]
__device__ unsigned g_WgLo[32 * 384];

// ---------------------------------------------------------------------------
// Math helpers
// ---------------------------------------------------------------------------
__device__ __forceinline__ float fast_tanh(float x) {
    float y;
    asm("tanh.approx.f32 %0, %1;" : "=f"(y) : "f"(x));
    return y;
}
__device__ __forceinline__ float fsigmoid(float x) {
    return __fdividef(1.0f, 1.0f + __expf(-x));
}
__device__ __forceinline__ float fsoftplus(float x) {
    return fmaxf(x, 0.0f) + log1pf(__expf(-fabsf(x)));
}
__device__ __forceinline__ float fgelu(float x) {
    return 0.5f * x * (1.0f + erff(x * 0.70710678118654752f));
}
// pack two f32 -> bf16x2 (lo = first element in lower 16 bits)
__device__ __forceinline__ unsigned bfpair(float lo, float hi) {
    unsigned r;
    asm("cvt.rn.bf16x2.f32 %0, %1, %2;" : "=r"(r) : "f"(hi), "f"(lo));
    return r;
}
// split a float2 (consecutive-k pair) into hi/lo bf16x2 regs
__device__ __forceinline__ void split2(float2 e, unsigned& h, unsigned& l) {
    unsigned hp = bfpair(e.x, e.y);
    float h0 = __uint_as_float(hp << 16);
    float h1 = __uint_as_float(hp & 0xFFFF0000u);
    h = hp;
    l = bfpair(e.x - h0, e.y - h1);
}
__device__ __forceinline__ void mma_bf16(float* c, const unsigned* a, unsigned b0, unsigned b1) {
    asm volatile(
        "mma.sync.aligned.m16n8k16.row.col.f32.bf16.bf16.f32 "
        "{%0,%1,%2,%3}, {%4,%5,%6,%7}, {%8,%9}, {%0,%1,%2,%3};"
        : "+f"(c[0]), "+f"(c[1]), "+f"(c[2]), "+f"(c[3])
        : "r"(a[0]), "r"(a[1]), "r"(a[2]), "r"(a[3]), "r"(b0), "r"(b1));
}

// ---------------------------------------------------------------------------
// Setup: wt[c] = sum_d Wtime[d]*Wg[64+d,c]; bias[c] = sum_d btime[d]*Wg[64+d,c] + bg[c]
// ---------------------------------------------------------------------------
__global__ void setup_kernel(const float* __restrict__ Wtime, const float* __restrict__ btime,
                             const float* __restrict__ Wg, const float* __restrict__ bg) {
    int c = threadIdx.x;   // 384 threads
    float s1 = 0.f, s2 = 0.f;
    #pragma unroll 8
    for (int d = 0; d < 64; d++) {
        float w = Wg[(size_t)(64 + d) * 384 + c];
        s1 += Wtime[d] * w;
        s2 += btime[d] * w;
    }
    g_wt[c] = s1;
    g_bias[c] = s2 + bg[c];
}

// Split We[768,64] into packed bf16x2 hi/lo planes: index t = j*64+n, j=k/2.
__global__ void split_we_kernel(const float* __restrict__ We) {
    int t = blockIdx.x * 256 + threadIdx.x;   // 0..24575
    if (t >= 384 * 64) return;
    int j = t >> 6, n = t & 63;
    float2 e = make_float2(We[(size_t)(2 * j) * 64 + n], We[(size_t)(2 * j + 1) * 64 + n]);
    unsigned h, l;
    split2(e, h, l);
    g_WeHi[t] = h;
    g_WeLo[t] = l;
}

// Split Wg_top[64,384] into packed bf16x2 hi/lo planes: t = j*384+n, j = k/2 (0..31).
__global__ void split_wg_kernel(const float* __restrict__ Wg) {
    int t = blockIdx.x * 256 + threadIdx.x;   // 0..12287
    if (t >= 32 * 384) return;
    int j = t / 384, n = t - j * 384;
    float2 e = make_float2(Wg[(size_t)(2 * j) * 384 + n], Wg[(size_t)(2 * j + 1) * 384 + n]);
    unsigned h, l;
    split2(e, h, l);
    g_WgHi[t] = h;
    g_WgLo[t] = l;
}

// ---------------------------------------------------------------------------
// GEMM1 via bf16-split tensor-core mma. MERGED: blocks [0,NEVB) = event rows,
// blocks [NEVB,NEVB+2) = cls rows (riding the same wave).
// ---------------------------------------------------------------------------
__global__ __launch_bounds__(256) void gemm1_mma(const float* __restrict__ Aev,
                                                 const float* __restrict__ Acls,
                                                 const unsigned* __restrict__ BHi,
                                                 const unsigned* __restrict__ BLo,
                                                 const float* __restrict__ be,
                                                 float* __restrict__ Cev,
                                                 float* __restrict__ Ccls) {
    __shared__ __align__(16) float As[2][128][20];        // [m][k] + pad (80B rows)
    __shared__ __align__(16) unsigned BsH[2][8][64];      // [j][n] packed bf16x2
    __shared__ __align__(16) unsigned BsL[2][8][64];
    const int tid = threadIdx.x;
    const int wid = tid >> 5, lane = tid & 31;
    const int warpR = wid >> 1;          // 0..3 : rows warpR*32
    const int warpC = wid & 1;           // 0..1 : cols warpC*32
    const int q = lane & 3, rr = lane >> 2;

    const float* A;
    float* C;
    size_t r0;
    if (blockIdx.x < NEVB) {
        A = Aev;  C = Cev;  r0 = (size_t)blockIdx.x * 128;
    } else {
        A = Acls; C = Ccls; r0 = (size_t)(blockIdx.x - NEVB) * 128;
    }

    float acc[2][4][4];
    #pragma unroll
    for (int mt = 0; mt < 2; mt++)
        #pragma unroll
        for (int nt = 0; nt < 4; nt++)
            #pragma unroll
            for (int i = 0; i < 4; i++) acc[mt][nt][i] = 0.f;

    // tile 0 loads
    {
        #pragma unroll
        for (int p = 0; p < 2; p++) {
            int idx = tid + p * 256;
            int m = idx >> 2, kv = (idx & 3) * 4;
            *reinterpret_cast<float4*>(&As[0][m][kv]) =
                *reinterpret_cast<const float4*>(A + (r0 + m) * 768 + kv);
        }
        *reinterpret_cast<uint2*>(&BsH[0][0][0] + tid * 2) =
            *reinterpret_cast<const uint2*>(BHi + tid * 2);
        *reinterpret_cast<uint2*>(&BsL[0][0][0] + tid * 2) =
            *reinterpret_cast<const uint2*>(BLo + tid * 2);
    }
    __syncthreads();

    #pragma unroll 2
    for (int t = 0; t < 48; t++) {
        int cur = t & 1;
        if (t < 47) {
            int nxt = cur ^ 1;
            int k0 = (t + 1) * 16;
            #pragma unroll
            for (int p = 0; p < 2; p++) {
                int idx = tid + p * 256;
                int m = idx >> 2, kv = (idx & 3) * 4;
                *reinterpret_cast<float4*>(&As[nxt][m][kv]) =
                    *reinterpret_cast<const float4*>(A + (r0 + m) * 768 + k0 + kv);
            }
            size_t jb = (size_t)(t + 1) * 8 * 64;
            *reinterpret_cast<uint2*>(&BsH[nxt][0][0] + tid * 2) =
                *reinterpret_cast<const uint2*>(BHi + jb + tid * 2);
            *reinterpret_cast<uint2*>(&BsL[nxt][0][0] + tid * 2) =
                *reinterpret_cast<const uint2*>(BLo + jb + tid * 2);
        }

        unsigned aH[2][4], aL[2][4];
        #pragma unroll
        for (int mt = 0; mt < 2; mt++) {
            int row = warpR * 32 + mt * 16 + rr;
            #pragma unroll
            for (int kk = 0; kk < 2; kk++) {
                float2 e0 = *reinterpret_cast<const float2*>(&As[cur][row][2 * q + 8 * kk]);
                float2 e1 = *reinterpret_cast<const float2*>(&As[cur][row + 8][2 * q + 8 * kk]);
                split2(e0, aH[mt][2 * kk + 0], aL[mt][2 * kk + 0]);
                split2(e1, aH[mt][2 * kk + 1], aL[mt][2 * kk + 1]);
            }
        }
        #pragma unroll
        for (int nt = 0; nt < 4; nt++) {
            int c = warpC * 32 + nt * 8 + rr;
            unsigned bH0 = BsH[cur][q][c],     bH1 = BsH[cur][q + 4][c];
            unsigned bL0 = BsL[cur][q][c],     bL1 = BsL[cur][q + 4][c];
            #pragma unroll
            for (int mt = 0; mt < 2; mt++) {
                mma_bf16(acc[mt][nt], aH[mt], bH0, bH1);
                mma_bf16(acc[mt][nt], aH[mt], bL0, bL1);
                mma_bf16(acc[mt][nt], aL[mt], bH0, bH1);
            }
        }
        __syncthreads();
    }

    // epilogue: + be, direct float2 stores
    #pragma unroll
    for (int nt = 0; nt < 4; nt++) {
        int col = warpC * 32 + nt * 8 + 2 * q;
        float b0 = be[col], b1 = be[col + 1];
        #pragma unroll
        for (int mt = 0; mt < 2; mt++) {
            size_t row = r0 + warpR * 32 + mt * 16 + rr;
            *reinterpret_cast<float2*>(C + row * 64 + col) =
                make_float2(acc[mt][nt][0] + b0, acc[mt][nt][1] + b1);
            *reinterpret_cast<float2*>(C + (row + 8) * 64 + col) =
                make_float2(acc[mt][nt][2] + b0, acc[mt][nt][3] + b1);
        }
    }
}

// ---------------------------------------------------------------------------
// GEMM2 via bf16-split tensor-core mma:
//   gates = act( E[128,64] @ Wg_top[64,384] + days*wt + bias )
// Grid (NEVB+2, 3): x selects row block (event/cls), y selects 128-col slab.
// E split hi/lo ONCE into smem; Wg pre-split globally; K=64 in 4 chunks.
// Per warp: 32 rows x 64 cols (2 m-tiles x 8 n-tiles).
// ---------------------------------------------------------------------------
__global__ __launch_bounds__(256, 2) void gemm2_mma(const float* __restrict__ Eev,
                                                    const float* __restrict__ Ecls,
                                                    const unsigned* __restrict__ WgHi,
                                                    const unsigned* __restrict__ WgLo,
                                                    const float* __restrict__ days_in,
                                                    float* __restrict__ Gev,
                                                    float* __restrict__ Gcls) {
    __shared__ unsigned AsH[128][33], AsL[128][33];       // 33.8 KB (odd pitch)
    __shared__ __align__(16) unsigned BsH[8][132], BsL[8][132];  // 8.4 KB, pitch 132
    const int tid = threadIdx.x;
    const int wid = tid >> 5, lane = tid & 31;
    const int warpR = wid >> 1;          // rows warpR*32
    const int warpC = wid & 1;           // cols warpC*64 within the 128 slab
    const int q = lane & 3, rr = lane >> 2;
    const int n0 = blockIdx.y * 128;

    const float* E;
    const float* days;
    float* gates;
    int M;
    size_t r0;
    if (blockIdx.x < NEVB) {
        E = Eev;  days = days_in; gates = Gev;  M = Mseq;
        r0 = (size_t)blockIdx.x * 128;
    } else {
        E = Ecls; days = nullptr; gates = Gcls; M = Bm;
        r0 = (size_t)(blockIdx.x - NEVB) * 128;
    }

    // load + split E tile once: 128 rows x 32 k-pairs
    #pragma unroll
    for (int p = 0; p < 16; p++) {
        int idx = tid + p * 256;
        int m = idx >> 5, j = idx & 31;
        float2 e = *reinterpret_cast<const float2*>(E + (r0 + m) * 64 + 2 * j);
        unsigned h, l;
        split2(e, h, l);
        AsH[m][j] = h;
        AsL[m][j] = l;
    }

    float acc[2][8][4];
    #pragma unroll
    for (int mt = 0; mt < 2; mt++)
        #pragma unroll
        for (int nt = 0; nt < 8; nt++)
            #pragma unroll
            for (int i = 0; i < 4; i++) acc[mt][nt][i] = 0.f;

    #pragma unroll
    for (int c = 0; c < 4; c++) {          // K chunks of 16 (8 k-pairs)
        __syncthreads();                    // (c=0: A visible; c>0: Bs reads done)
        {
            int t4 = tid * 4;
            int jj = t4 >> 7, nn = t4 & 127;
            size_t src = (size_t)(c * 8 + jj) * 384 + n0 + nn;
            *reinterpret_cast<uint4*>(&BsH[jj][nn]) = *reinterpret_cast<const uint4*>(WgHi + src);
            *reinterpret_cast<uint4*>(&BsL[jj][nn]) = *reinterpret_cast<const uint4*>(WgLo + src);
        }
        __syncthreads();

        unsigned aH[2][4], aL[2][4];
        const int jb = c * 8;
        #pragma unroll
        for (int mt = 0; mt < 2; mt++) {
            int row = warpR * 32 + mt * 16 + rr;
            aH[mt][0] = AsH[row][jb + q];         aL[mt][0] = AsL[row][jb + q];
            aH[mt][1] = AsH[row + 8][jb + q];     aL[mt][1] = AsL[row + 8][jb + q];
            aH[mt][2] = AsH[row][jb + q + 4];     aL[mt][2] = AsL[row][jb + q + 4];
            aH[mt][3] = AsH[row + 8][jb + q + 4]; aL[mt][3] = AsL[row + 8][jb + q + 4];
        }
        #pragma unroll
        for (int nt = 0; nt < 8; nt++) {
            int cc = warpC * 64 + nt * 8 + rr;
            unsigned bH0 = BsH[q][cc], bH1 = BsH[q + 4][cc];
            unsigned bL0 = BsL[q][cc], bL1 = BsL[q + 4][cc];
            #pragma unroll
            for (int mt = 0; mt < 2; mt++) {
                mma_bf16(acc[mt][nt], aH[mt], bH0, bH1);
                mma_bf16(acc[mt][nt], aH[mt], bL0, bL1);
                mma_bf16(acc[mt][nt], aL[mt], bH0, bH1);
            }
        }
    }

    // Epilogue: bias + rank-1 time term + activation (gate uniform per thread).
    const int gate = (n0 + warpC * 64) >> 6;
    float wt16[8][2], bi16[8][2];
    #pragma unroll
    for (int nt = 0; nt < 8; nt++) {
        int col = n0 + warpC * 64 + nt * 8 + 2 * q;
        wt16[nt][0] = g_wt[col];   wt16[nt][1] = g_wt[col + 1];
        bi16[nt][0] = g_bias[col]; bi16[nt][1] = g_bias[col + 1];
    }
    const int d0 = 2 * q;   // within-gate col base, + nt*8
    #pragma unroll
    for (int mt = 0; mt < 2; mt++) {
        size_t rowb = r0 + warpR * 32 + mt * 16 + rr;
        #pragma unroll
        for (int h = 0; h < 2; h++) {
            size_t rg = rowb + h * 8;
            float dy = days ? days[rg] : 0.f;
            float v[16];
            #pragma unroll
            for (int nt = 0; nt < 8; nt++) {
                v[2 * nt + 0] = acc[mt][nt][2 * h + 0] + bi16[nt][0] + dy * wt16[nt][0];
                v[2 * nt + 1] = acc[mt][nt][2 * h + 1] + bi16[nt][1] + dy * wt16[nt][1];
            }
            if (gate == 2) {
                #pragma unroll
                for (int i = 0; i < 16; i++) v[i] = fast_tanh(v[i]);
            } else if (gate == 4) {
                #pragma unroll
                for (int i = 0; i < 16; i++) v[i] = fsoftplus(v[i]);
            } else if (gate != 5) {   // 0,1,3 -> sigmoid
                #pragma unroll
                for (int i = 0; i < 16; i++) v[i] = fsigmoid(v[i]);
            }
            float* dst = gates + ((size_t)gate * M + rg) * 64 + d0;
            #pragma unroll
            for (int nt = 0; nt < 8; nt++)
                *reinterpret_cast<float2*>(dst + nt * 8) = make_float2(v[2 * nt], v[2 * nt + 1]);
        }
    }
}

// ---------------------------------------------------------------------------
// Chunk-parallel CT-LSTM scan (unchanged)
// ---------------------------------------------------------------------------
__global__ __launch_bounds__(256) void scanA_kernel(const float* __restrict__ gates) {
    int t = blockIdx.x * 256 + threadIdx.x;
    int d = t & 63, rest = t >> 6;
    int b = rest & 255, ch = rest >> 8;
    const size_t S = (size_t)Mseq * 64;
    size_t base = ((size_t)(b * Lm + ch * CL)) * 64 + d;
    float c = 0.f, P = 1.f;
    #pragma unroll 5
    for (int l = 0; l < CL; l++) {
        size_t idx = base + (size_t)l * 64;
        float i_ = gates[idx];
        float f_ = gates[S + idx];
        float z_ = gates[2 * S + idx];
        c = f_ * c + i_ * z_;
        P *= f_;
    }
    g_scanA[t] = c;
    g_scanP[t] = P;
}

__global__ __launch_bounds__(256) void scanB_kernel() {
    int t = blockIdx.x * 256 + threadIdx.x;
    float c = 0.f;
    #pragma unroll
    for (int ch = 0; ch < NC; ch++) {
        int q = ch * 16384 + t;
        g_scanCin[q] = c;
        c = g_scanP[q] * c + g_scanA[q];
    }
    g_Clast[t] = c;
}

__global__ __launch_bounds__(256) void scanC_kernel(const float* __restrict__ gates,
                                                    const float* __restrict__ days) {
    int t = blockIdx.x * 256 + threadIdx.x;
    int d = t & 63, rest = t >> 6;
    int b = rest & 255, ch = rest >> 8;
    const size_t S = (size_t)Mseq * 64;
    size_t base = ((size_t)(b * Lm + ch * CL)) * 64 + d;
    const float* dptr = days + b * Lm + ch * CL;
    float c = g_scanCin[t];
    #pragma unroll 5
    for (int l = 0; l < CL; l++) {
        size_t idx = base + (size_t)l * 64;
        float i_ = gates[idx];
        float f_ = gates[S + idx];
        float z_ = gates[2 * S + idx];
        float o_ = gates[3 * S + idx];
        float dl = gates[4 * S + idx];
        float cb = gates[5 * S + idx];
        float dt = fmaxf(dptr[l], 0.f);
        c = f_ * c + i_ * z_;
        float e = __expf(-dl * dt);
        float cd = cb + (c - cb) * e;
        g_Hs[idx] = o_ * fast_tanh(cd);
    }
}

// ---------------------------------------------------------------------------
// Final CT-LSTM step at dt = 0
// ---------------------------------------------------------------------------
__global__ void final_ch_kernel() {
    int b = blockIdx.x, d = threadIdx.x;
    const int S = Bm * 64;
    int idx = b * 64 + d;
    float c = g_Gc[S + idx] * g_Clast[idx] + g_Gc[idx] * g_Gc[2 * S + idx];
    g_Hcur[idx] = g_Gc[3 * S + idx] * fast_tanh(c);
}

// ---------------------------------------------------------------------------
// Intensity MLP (unchanged; Ys aliased into rows buffer)
// ---------------------------------------------------------------------------
__global__ __launch_bounds__(256) void intensity_kernel(const float* __restrict__ src, int M,
                                                        const float* __restrict__ W1,
                                                        const float* __restrict__ b1,
                                                        const float* __restrict__ W2,
                                                        const float* __restrict__ b2,
                                                        float* __restrict__ out) {
    __shared__ __align__(16) float rows[128][68];
    __shared__ __align__(16) float W1s[2048];
    __shared__ float W2s[192], b1s[32], b2s[6];
    float* Ys = &rows[0][0];
    int tid = threadIdx.x;
    size_t r0 = (size_t)blockIdx.x * 128;

    for (int i4 = tid; i4 < 512; i4 += 256)
        *reinterpret_cast<float4*>(&W1s[i4 * 4]) = reinterpret_cast<const float4*>(W1)[i4];
    if (tid < 192) W2s[tid] = W2[tid];
    if (tid < 32) b1s[tid] = b1[tid];
    if (tid < 6) b2s[tid] = b2[tid];
    #pragma unroll
    for (int p = 0; p < 8; p++) {
        int idx = tid + p * 256;
        int m = idx >> 4, dv = (idx & 15) * 4;
        *reinterpret_cast<float4*>(&rows[m][dv]) =
            *reinterpret_cast<const float4*>(src + (r0 + m) * 64 + dv);
    }
    __syncthreads();

    int tr = tid >> 3, tc = tid & 7;
    float acc[4][4];
    #pragma unroll
    for (int i = 0; i < 4; i++)
        #pragma unroll
        for (int j = 0; j < 4; j++) acc[i][j] = b1s[tc * 4 + j];
    #pragma unroll 4
    for (int k = 0; k < 64; k++) {
        float4 w = *reinterpret_cast<const float4*>(&W1s[k * 32 + tc * 4]);
        float a0 = rows[tr * 4 + 0][k];
        float a1 = rows[tr * 4 + 1][k];
        float a2 = rows[tr * 4 + 2][k];
        float a3 = rows[tr * 4 + 3][k];
        acc[0][0] = fmaf(a0, w.x, acc[0][0]); acc[0][1] = fmaf(a0, w.y, acc[0][1]);
        acc[0][2] = fmaf(a0, w.z, acc[0][2]); acc[0][3] = fmaf(a0, w.w, acc[0][3]);
        acc[1][0] = fmaf(a1, w.x, acc[1][0]); acc[1][1] = fmaf(a1, w.y, acc[1][1]);
        acc[1][2] = fmaf(a1, w.z, acc[1][2]); acc[1][3] = fmaf(a1, w.w, acc[1][3]);
        acc[2][0] = fmaf(a2, w.x, acc[2][0]); acc[2][1] = fmaf(a2, w.y, acc[2][1]);
        acc[2][2] = fmaf(a2, w.z, acc[2][2]); acc[2][3] = fmaf(a2, w.w, acc[2][3]);
        acc[3][0] = fmaf(a3, w.x, acc[3][0]); acc[3][1] = fmaf(a3, w.y, acc[3][1]);
        acc[3][2] = fmaf(a3, w.z, acc[3][2]); acc[3][3] = fmaf(a3, w.w, acc[3][3]);
    }
    __syncthreads();
    #pragma unroll
    for (int i = 0; i < 4; i++)
        #pragma unroll
        for (int j = 0; j < 4; j++)
            Ys[(tr * 4 + i) * 33 + tc * 4 + j] = fgelu(acc[i][j]);
    __syncthreads();

    if (tid < 128) {
        int row = tid;
        float o6[6];
        #pragma unroll
        for (int c = 0; c < 6; c++) o6[c] = b2s[c];
        #pragma unroll 4
        for (int k = 0; k < 32; k++) {
            float a = Ys[row * 33 + k];
            #pragma unroll
            for (int c = 0; c < 6; c++) o6[c] = fmaf(a, W2s[k * 6 + c], o6[c]);
        }
        #pragma unroll
        for (int c = 0; c < 6; c++) out[(r0 + row) * 6 + c] = fsoftplus(o6[c]);
    }
}

// ---------------------------------------------------------------------------
// TTE head (unchanged)
// ---------------------------------------------------------------------------
__global__ __launch_bounds__(256) void tte_kernel(const float* __restrict__ W1,
                                                  const float* __restrict__ b1,
                                                  const float* __restrict__ W2,
                                                  const float* __restrict__ b2,
                                                  float* __restrict__ out) {
    __shared__ float W1s[64 * 32];
    __shared__ float W2s[32];
    __shared__ float b1s[32];
    __shared__ float b2s0;
    __shared__ float rows[8][64];
    int tid = threadIdx.x;
    for (int i = tid; i < 2048; i += 256) W1s[i] = W1[i];
    if (tid < 32) { W2s[tid] = W2[tid]; b1s[tid] = b1[tid]; }
    if (tid == 0) b2s0 = b2[0];
    __syncthreads();
    int warp = tid >> 5, lane = tid & 31;
    int b = blockIdx.x * 8 + warp;
    if (b >= Bm) return;
    rows[warp][lane] = g_Hcur[b * 64 + lane];
    rows[warp][lane + 32] = g_Hcur[b * 64 + lane + 32];
    __syncwarp();
    float acc = b1s[lane];
    #pragma unroll
    for (int k = 0; k < 64; k++) acc = fmaf(rows[warp][k], W1s[k * 32 + lane], acc);
    float y = fgelu(acc);
    float p = y * W2s[lane];
    #pragma unroll
    for (int off = 16; off; off >>= 1) p += __shfl_xor_sync(0xffffffffu, p, off);
    if (lane == 0) out[b] = fsoftplus(p + b2s0);
}

// ---------------------------------------------------------------------------
// Direct head + softmax (unchanged)
// ---------------------------------------------------------------------------
__global__ __launch_bounds__(384) void direct_kernel(const float* __restrict__ cls,
                                                     const float* __restrict__ Ws1,
                                                     const float* __restrict__ bs1,
                                                     const float* __restrict__ Ws2,
                                                     const float* __restrict__ bs2,
                                                     const float* __restrict__ ci,
                                                     float* __restrict__ probs) {
    __shared__ float cls_s[4 * 768];
    __shared__ float s1[4][384];
    __shared__ float logit_s[4][6];
    int tid = threadIdx.x;
    int b0 = blockIdx.x * 4;
    for (int idx = tid; idx < 4 * 768; idx += 384)
        cls_s[idx] = cls[(size_t)b0 * 768 + idx];
    __syncthreads();
    float a0 = bs1[tid], a1 = a0, a2 = a0, a3 = a0;
    #pragma unroll 4
    for (int k = 0; k < 768; k++) {
        float w = Ws1[(size_t)k * 384 + tid];
        a0 = fmaf(cls_s[k], w, a0);
        a1 = fmaf(cls_s[768 + k], w, a1);
        a2 = fmaf(cls_s[1536 + k], w, a2);
        a3 = fmaf(cls_s[2304 + k], w, a3);
    }
    s1[0][tid] = fgelu(a0);
    s1[1][tid] = fgelu(a1);
    s1[2][tid] = fgelu(a2);
    s1[3][tid] = fgelu(a3);
    __syncthreads();
    int w = tid >> 5, lane = tid & 31;
    if (w < 6) {
        for (int g = 0; g < 4; g++) {
            float p = 0.f;
            #pragma unroll
            for (int j = lane; j < 384; j += 32) p = fmaf(s1[g][j], Ws2[(size_t)j * 6 + w], p);
            #pragma unroll
            for (int off = 16; off; off >>= 1) p += __shfl_xor_sync(0xffffffffu, p, off);
            if (lane == 0) logit_s[g][w] = p + bs2[w];
        }
    }
    __syncthreads();
    if (tid < 4) {
        int g = tid;
        float x[6], m = -1e30f;
        #pragma unroll
        for (int c = 0; c < 6; c++) {
            x[c] = logit_s[g][c] + logf(ci[(size_t)(b0 + g) * 6 + c]);
            m = fmaxf(m, x[c]);
        }
        float s = 0.f;
        #pragma unroll
        for (int c = 0; c < 6; c++) { x[c] = __expf(x[c] - m); s += x[c]; }
        float inv = __fdividef(1.f, s);
        #pragma unroll
        for (int c = 0; c < 6; c++) probs[(size_t)(b0 + g) * 6 + c] = x[c] * inv;
    }
}

// ---------------------------------------------------------------------------
// Launch
// ---------------------------------------------------------------------------
extern "C" void kernel_launch(void* const* d_in, const int* in_sizes, int n_in,
                              void* d_out, int out_size) {
    const float* cls   = (const float*)d_in[0];
    const float* ev    = (const float*)d_in[1];
    const float* days  = (const float*)d_in[2];
    const float* We    = (const float*)d_in[3];
    const float* be    = (const float*)d_in[4];
    const float* Wtime = (const float*)d_in[5];
    const float* btime = (const float*)d_in[6];
    const float* Wg    = (const float*)d_in[7];
    const float* bg    = (const float*)d_in[8];
    const float* Wi1   = (const float*)d_in[9];
    const float* bi1   = (const float*)d_in[10];
    const float* Wi2   = (const float*)d_in[11];
    const float* bi2   = (const float*)d_in[12];
    const float* Ws1   = (const float*)d_in[13];
    const float* bs1   = (const float*)d_in[14];
    const float* Ws2   = (const float*)d_in[15];
    const float* bs2   = (const float*)d_in[16];
    const float* Wq1   = (const float*)d_in[17];
    const float* bq1   = (const float*)d_in[18];
    const float* Wq2   = (const float*)d_in[19];
    const float* bq2   = (const float*)d_in[20];

    float* out = (float*)d_out;
    float* out_probs = out;
    float* out_tte   = out + 1536;
    float* out_ci    = out + 1536 + 256;
    float* out_hist  = out + 1536 + 256 + 1536;

    float *pE, *pG, *pEc, *pGc, *pHs, *pHcur;
    unsigned *pWeHi, *pWeLo, *pWgHi, *pWgLo;
    cudaGetSymbolAddress((void**)&pE, g_E);
    cudaGetSymbolAddress((void**)&pG, g_G);
    cudaGetSymbolAddress((void**)&pEc, g_Ec);
    cudaGetSymbolAddress((void**)&pGc, g_Gc);
    cudaGetSymbolAddress((void**)&pHs, g_Hs);
    cudaGetSymbolAddress((void**)&pHcur, g_Hcur);
    cudaGetSymbolAddress((void**)&pWeHi, g_WeHi);
    cudaGetSymbolAddress((void**)&pWeLo, g_WeLo);
    cudaGetSymbolAddress((void**)&pWgHi, g_WgHi);
    cudaGetSymbolAddress((void**)&pWgLo, g_WgLo);

    setup_kernel<<<1, 384>>>(Wtime, btime, Wg, bg);
    split_we_kernel<<<96, 256>>>(We);
    split_wg_kernel<<<48, 256>>>(Wg);

    gemm1_mma<<<NEVB + 2, 256>>>(ev, cls, pWeHi, pWeLo, be, pE, pEc);
    gemm2_mma<<<dim3(NEVB + 2, 3), 256>>>(pE, pEc, pWgHi, pWgLo, days, pG, pGc);

    scanA_kernel<<<(Bm * Dm * NC) / 256, 256>>>(pG);
    scanB_kernel<<<(Bm * Dm) / 256, 256>>>();
    scanC_kernel<<<(Bm * Dm * NC) / 256, 256>>>(pG, days);
    final_ch_kernel<<<Bm, 64>>>();

    intensity_kernel<<<Mseq / 128, 256>>>(pHs, Mseq, Wi1, bi1, Wi2, bi2, out_hist);
    intensity_kernel<<<Bm / 128, 256>>>(pHcur, Bm, Wi1, bi1, Wi2, bi2, out_ci);
    tte_kernel<<<Bm / 8, 256>>>(Wq1, bq1, Wq2, bq2, out_tte);
    direct_kernel<<<Bm / 4, 384>>>(cls, Ws1, bs1, Ws2, bs2, out_ci, out_probs);
}

// round 11
// speedup vs baseline: 1.4789x; 1.1933x over previous
#include <cuda_runtime.h>
#include <cuda_bf16.h>
#include <math.h>
#include <stdint.h>

// ---------------------------------------------------------------------------
// Problem constants
// ---------------------------------------------------------------------------
#define Bm 256
#define Lm 200
#define Hm 768
#define Dm 64
#define NS 6
#define Mseq (Bm * Lm)          // 51200
#define NC 8                    // scan chunks
#define CL 25                   // Lm / NC
#define NEVB (Mseq / 128)       // 400 blocks for the sequence rows

typedef unsigned long long ull;

// ---------------------------------------------------------------------------
// Device scratch (static globals — no allocation allowed)
// ---------------------------------------------------------------------------
__device__ float g_E[(size_t)Mseq * Dm];            // E = ev@We+be
__device__ float g_G[(size_t)6 * Mseq * Dm];        // activated gates (gate, row, d)
__device__ float g_Hs[(size_t)Mseq * Dm];           // hidden states
__device__ float g_Ec[Bm * Dm];
__device__ float g_Gc[6 * Bm * Dm];
__device__ float g_Clast[Bm * Dm];
__device__ float g_Hcur[Bm * Dm];
__device__ float g_wt[384];                          // Wtime @ Wg_bot
__device__ float g_bias[384];                        // btime @ Wg_bot + bg
__device__ float g_scanP[Bm * Dm * NC];              // chunk prod(f)
__device__ float g_scanA[Bm * Dm * NC];              // chunk affine term
__device__ float g_scanCin[Bm * Dm * NC];            // chunk entry carry
__device__ unsigned g_WeHi[384 * 64];                // We split: packed bf16x2 (k pairs)
__device__ unsigned g_WeLo[384 * 64];
__device__ unsigned g_WgHi[32 * 384];                // Wg_top split: [kpair][n]
__device__ unsigned g_WgLo[32 * 384];

// ---------------------------------------------------------------------------
// Math helpers
// ---------------------------------------------------------------------------
__device__ __forceinline__ float fast_tanh(float x) {
    float y;
    asm("tanh.approx.f32 %0, %1;" : "=f"(y) : "f"(x));
    return y;
}
__device__ __forceinline__ float fsigmoid(float x) {
    return __fdividef(1.0f, 1.0f + __expf(-x));
}
__device__ __forceinline__ float fsoftplus(float x) {
    return fmaxf(x, 0.0f) + log1pf(__expf(-fabsf(x)));
}
__device__ __forceinline__ float fgelu(float x) {
    return 0.5f * x * (1.0f + erff(x * 0.70710678118654752f));
}
// pack two f32 -> bf16x2 (lo = first element in lower 16 bits)
__device__ __forceinline__ unsigned bfpair(float lo, float hi) {
    unsigned r;
    asm("cvt.rn.bf16x2.f32 %0, %1, %2;" : "=r"(r) : "f"(hi), "f"(lo));
    return r;
}
// split a float2 (consecutive-k pair) into hi/lo bf16x2 regs
__device__ __forceinline__ void split2(float2 e, unsigned& h, unsigned& l) {
    unsigned hp = bfpair(e.x, e.y);
    float h0 = __uint_as_float(hp << 16);
    float h1 = __uint_as_float(hp & 0xFFFF0000u);
    h = hp;
    l = bfpair(e.x - h0, e.y - h1);
}
__device__ __forceinline__ void mma_bf16(float* c, const unsigned* a, unsigned b0, unsigned b1) {
    asm volatile(
        "mma.sync.aligned.m16n8k16.row.col.f32.bf16.bf16.f32 "
        "{%0,%1,%2,%3}, {%4,%5,%6,%7}, {%8,%9}, {%0,%1,%2,%3};"
        : "+f"(c[0]), "+f"(c[1]), "+f"(c[2]), "+f"(c[3])
        : "r"(a[0]), "r"(a[1]), "r"(a[2]), "r"(a[3]), "r"(b0), "r"(b1));
}
__device__ __forceinline__ void cp_async16(void* sdst, const void* gsrc) {
    unsigned sa = (unsigned)__cvta_generic_to_shared(sdst);
    asm volatile("cp.async.cg.shared.global [%0], [%1], 16;" :: "r"(sa), "l"(gsrc) : "memory");
}

// ---------------------------------------------------------------------------
// Setup: wt[c] = sum_d Wtime[d]*Wg[64+d,c]; bias[c] = sum_d btime[d]*Wg[64+d,c] + bg[c]
// ---------------------------------------------------------------------------
__global__ void setup_kernel(const float* __restrict__ Wtime, const float* __restrict__ btime,
                             const float* __restrict__ Wg, const float* __restrict__ bg) {
    int c = threadIdx.x;   // 384 threads
    float s1 = 0.f, s2 = 0.f;
    #pragma unroll 8
    for (int d = 0; d < 64; d++) {
        float w = Wg[(size_t)(64 + d) * 384 + c];
        s1 += Wtime[d] * w;
        s2 += btime[d] * w;
    }
    g_wt[c] = s1;
    g_bias[c] = s2 + bg[c];
}

// Split We[768,64] into packed bf16x2 hi/lo planes: index t = j*64+n, j=k/2.
__global__ void split_we_kernel(const float* __restrict__ We) {
    int t = blockIdx.x * 256 + threadIdx.x;   // 0..24575
    if (t >= 384 * 64) return;
    int j = t >> 6, n = t & 63;
    float2 e = make_float2(We[(size_t)(2 * j) * 64 + n], We[(size_t)(2 * j + 1) * 64 + n]);
    unsigned h, l;
    split2(e, h, l);
    g_WeHi[t] = h;
    g_WeLo[t] = l;
}

// Split Wg_top[64,384] into packed bf16x2 hi/lo planes: t = j*384+n, j = k/2 (0..31).
__global__ void split_wg_kernel(const float* __restrict__ Wg) {
    int t = blockIdx.x * 256 + threadIdx.x;   // 0..12287
    if (t >= 32 * 384) return;
    int j = t / 384, n = t - j * 384;
    float2 e = make_float2(Wg[(size_t)(2 * j) * 384 + n], Wg[(size_t)(2 * j + 1) * 384 + n]);
    unsigned h, l;
    split2(e, h, l);
    g_WgHi[t] = h;
    g_WgLo[t] = l;
}

// ---------------------------------------------------------------------------
// GEMM1 via bf16-split tensor-core mma + 3-buffer cp.async pipeline
// (prefetch distance 2). MERGED: blocks [0,NEVB) = event rows,
// blocks [NEVB,NEVB+2) = cls rows.
// ---------------------------------------------------------------------------
#define G1_LOAD(s, t) do {                                                        \
    int k0_ = (t) * 16;                                                           \
    {   int m_ = tid >> 2, kv_ = (tid & 3) * 4;                                   \
        cp_async16(&As[s][m_][kv_], A + (r0 + m_) * 768 + k0_ + kv_); }           \
    {   int c_ = tid + 256;                                                       \
        int m_ = c_ >> 2, kv_ = (c_ & 3) * 4;                                     \
        cp_async16(&As[s][m_][kv_], A + (r0 + m_) * 768 + k0_ + kv_); }           \
    if (tid < 128) {                                                              \
        int j_ = tid >> 4, n_ = (tid & 15) * 4;                                   \
        cp_async16(&BsH[s][j_][n_], BHi + (size_t)(t) * 512 + j_ * 64 + n_);      \
    } else {                                                                      \
        int j_ = (tid - 128) >> 4, n_ = ((tid - 128) & 15) * 4;                   \
        cp_async16(&BsL[s][j_][n_], BLo + (size_t)(t) * 512 + j_ * 64 + n_);      \
    }                                                                             \
} while (0)

__global__ __launch_bounds__(256, 3) void gemm1_mma(const float* __restrict__ Aev,
                                                    const float* __restrict__ Acls,
                                                    const unsigned* __restrict__ BHi,
                                                    const unsigned* __restrict__ BLo,
                                                    const float* __restrict__ be,
                                                    float* __restrict__ Cev,
                                                    float* __restrict__ Ccls) {
    __shared__ __align__(16) float As[3][128][20];        // 30.0 KB
    __shared__ __align__(16) unsigned BsH[3][8][64];      // 6.0 KB
    __shared__ __align__(16) unsigned BsL[3][8][64];      // 6.0 KB
    const int tid = threadIdx.x;
    const int wid = tid >> 5, lane = tid & 31;
    const int warpR = wid >> 1;          // 0..3 : rows warpR*32
    const int warpC = wid & 1;           // 0..1 : cols warpC*32
    const int q = lane & 3, rr = lane >> 2;

    const float* A;
    float* C;
    size_t r0;
    if (blockIdx.x < NEVB) {
        A = Aev;  C = Cev;  r0 = (size_t)blockIdx.x * 128;
    } else {
        A = Acls; C = Ccls; r0 = (size_t)(blockIdx.x - NEVB) * 128;
    }

    float acc[2][4][4];
    #pragma unroll
    for (int mt = 0; mt < 2; mt++)
        #pragma unroll
        for (int nt = 0; nt < 4; nt++)
            #pragma unroll
            for (int i = 0; i < 4; i++) acc[mt][nt][i] = 0.f;

    // prologue: stages 0 and 1 in flight
    G1_LOAD(0, 0);
    asm volatile("cp.async.commit_group;" ::: "memory");
    G1_LOAD(1, 1);
    asm volatile("cp.async.commit_group;" ::: "memory");

    #pragma unroll 3
    for (int t = 0; t < 48; t++) {
        const int cur = t % 3;
        asm volatile("cp.async.wait_group 1;" ::: "memory");   // stage t resident
        __syncthreads();                                        // all warps past stage t-1 reads

        // issue stage t+2 into buffer (t+2)%3 (== buffer read at iter t-1)
        if (t + 2 < 48) {
            const int nxt = (t + 2) % 3;
            G1_LOAD(nxt, t + 2);
        }
        asm volatile("cp.async.commit_group;" ::: "memory");    // (possibly empty) group

        // compute stage cur
        unsigned aH[2][4], aL[2][4];
        #pragma unroll
        for (int mt = 0; mt < 2; mt++) {
            int row = warpR * 32 + mt * 16 + rr;
            #pragma unroll
            for (int kk = 0; kk < 2; kk++) {
                float2 e0 = *reinterpret_cast<const float2*>(&As[cur][row][2 * q + 8 * kk]);
                float2 e1 = *reinterpret_cast<const float2*>(&As[cur][row + 8][2 * q + 8 * kk]);
                split2(e0, aH[mt][2 * kk + 0], aL[mt][2 * kk + 0]);
                split2(e1, aH[mt][2 * kk + 1], aL[mt][2 * kk + 1]);
            }
        }
        #pragma unroll
        for (int nt = 0; nt < 4; nt++) {
            int c = warpC * 32 + nt * 8 + rr;
            unsigned bH0 = BsH[cur][q][c],     bH1 = BsH[cur][q + 4][c];
            unsigned bL0 = BsL[cur][q][c],     bL1 = BsL[cur][q + 4][c];
            #pragma unroll
            for (int mt = 0; mt < 2; mt++) {
                mma_bf16(acc[mt][nt], aH[mt], bH0, bH1);
                mma_bf16(acc[mt][nt], aH[mt], bL0, bL1);
                mma_bf16(acc[mt][nt], aL[mt], bH0, bH1);
            }
        }
    }

    // epilogue: + be, direct float2 stores
    #pragma unroll
    for (int nt = 0; nt < 4; nt++) {
        int col = warpC * 32 + nt * 8 + 2 * q;
        float b0 = be[col], b1 = be[col + 1];
        #pragma unroll
        for (int mt = 0; mt < 2; mt++) {
            size_t row = r0 + warpR * 32 + mt * 16 + rr;
            *reinterpret_cast<float2*>(C + row * 64 + col) =
                make_float2(acc[mt][nt][0] + b0, acc[mt][nt][1] + b1);
            *reinterpret_cast<float2*>(C + (row + 8) * 64 + col) =
                make_float2(acc[mt][nt][2] + b0, acc[mt][nt][3] + b1);
        }
    }
}

// ---------------------------------------------------------------------------
// GEMM2 via bf16-split tensor-core mma (unchanged from R10)
// ---------------------------------------------------------------------------
__global__ __launch_bounds__(256, 2) void gemm2_mma(const float* __restrict__ Eev,
                                                    const float* __restrict__ Ecls,
                                                    const unsigned* __restrict__ WgHi,
                                                    const unsigned* __restrict__ WgLo,
                                                    const float* __restrict__ days_in,
                                                    float* __restrict__ Gev,
                                                    float* __restrict__ Gcls) {
    __shared__ unsigned AsH[128][33], AsL[128][33];
    __shared__ __align__(16) unsigned BsH[8][132], BsL[8][132];
    const int tid = threadIdx.x;
    const int wid = tid >> 5, lane = tid & 31;
    const int warpR = wid >> 1;
    const int warpC = wid & 1;
    const int q = lane & 3, rr = lane >> 2;
    const int n0 = blockIdx.y * 128;

    const float* E;
    const float* days;
    float* gates;
    int M;
    size_t r0;
    if (blockIdx.x < NEVB) {
        E = Eev;  days = days_in; gates = Gev;  M = Mseq;
        r0 = (size_t)blockIdx.x * 128;
    } else {
        E = Ecls; days = nullptr; gates = Gcls; M = Bm;
        r0 = (size_t)(blockIdx.x - NEVB) * 128;
    }

    #pragma unroll
    for (int p = 0; p < 16; p++) {
        int idx = tid + p * 256;
        int m = idx >> 5, j = idx & 31;
        float2 e = *reinterpret_cast<const float2*>(E + (r0 + m) * 64 + 2 * j);
        unsigned h, l;
        split2(e, h, l);
        AsH[m][j] = h;
        AsL[m][j] = l;
    }

    float acc[2][8][4];
    #pragma unroll
    for (int mt = 0; mt < 2; mt++)
        #pragma unroll
        for (int nt = 0; nt < 8; nt++)
            #pragma unroll
            for (int i = 0; i < 4; i++) acc[mt][nt][i] = 0.f;

    #pragma unroll
    for (int c = 0; c < 4; c++) {
        __syncthreads();
        {
            int t4 = tid * 4;
            int jj = t4 >> 7, nn = t4 & 127;
            size_t src = (size_t)(c * 8 + jj) * 384 + n0 + nn;
            *reinterpret_cast<uint4*>(&BsH[jj][nn]) = *reinterpret_cast<const uint4*>(WgHi + src);
            *reinterpret_cast<uint4*>(&BsL[jj][nn]) = *reinterpret_cast<const uint4*>(WgLo + src);
        }
        __syncthreads();

        unsigned aH[2][4], aL[2][4];
        const int jb = c * 8;
        #pragma unroll
        for (int mt = 0; mt < 2; mt++) {
            int row = warpR * 32 + mt * 16 + rr;
            aH[mt][0] = AsH[row][jb + q];         aL[mt][0] = AsL[row][jb + q];
            aH[mt][1] = AsH[row + 8][jb + q];     aL[mt][1] = AsL[row + 8][jb + q];
            aH[mt][2] = AsH[row][jb + q + 4];     aL[mt][2] = AsL[row][jb + q + 4];
            aH[mt][3] = AsH[row + 8][jb + q + 4]; aL[mt][3] = AsL[row + 8][jb + q + 4];
        }
        #pragma unroll
        for (int nt = 0; nt < 8; nt++) {
            int cc = warpC * 64 + nt * 8 + rr;
            unsigned bH0 = BsH[q][cc], bH1 = BsH[q + 4][cc];
            unsigned bL0 = BsL[q][cc], bL1 = BsL[q + 4][cc];
            #pragma unroll
            for (int mt = 0; mt < 2; mt++) {
                mma_bf16(acc[mt][nt], aH[mt], bH0, bH1);
                mma_bf16(acc[mt][nt], aH[mt], bL0, bL1);
                mma_bf16(acc[mt][nt], aL[mt], bH0, bH1);
            }
        }
    }

    const int gate = (n0 + warpC * 64) >> 6;
    float wt16[8][2], bi16[8][2];
    #pragma unroll
    for (int nt = 0; nt < 8; nt++) {
        int col = n0 + warpC * 64 + nt * 8 + 2 * q;
        wt16[nt][0] = g_wt[col];   wt16[nt][1] = g_wt[col + 1];
        bi16[nt][0] = g_bias[col]; bi16[nt][1] = g_bias[col + 1];
    }
    const int d0 = 2 * q;
    #pragma unroll
    for (int mt = 0; mt < 2; mt++) {
        size_t rowb = r0 + warpR * 32 + mt * 16 + rr;
        #pragma unroll
        for (int h = 0; h < 2; h++) {
            size_t rg = rowb + h * 8;
            float dy = days ? days[rg] : 0.f;
            float v[16];
            #pragma unroll
            for (int nt = 0; nt < 8; nt++) {
                v[2 * nt + 0] = acc[mt][nt][2 * h + 0] + bi16[nt][0] + dy * wt16[nt][0];
                v[2 * nt + 1] = acc[mt][nt][2 * h + 1] + bi16[nt][1] + dy * wt16[nt][1];
            }
            if (gate == 2) {
                #pragma unroll
                for (int i = 0; i < 16; i++) v[i] = fast_tanh(v[i]);
            } else if (gate == 4) {
                #pragma unroll
                for (int i = 0; i < 16; i++) v[i] = fsoftplus(v[i]);
            } else if (gate != 5) {
                #pragma unroll
                for (int i = 0; i < 16; i++) v[i] = fsigmoid(v[i]);
            }
            float* dst = gates + ((size_t)gate * M + rg) * 64 + d0;
            #pragma unroll
            for (int nt = 0; nt < 8; nt++)
                *reinterpret_cast<float2*>(dst + nt * 8) = make_float2(v[2 * nt], v[2 * nt + 1]);
        }
    }
}

// ---------------------------------------------------------------------------
// Chunk-parallel CT-LSTM scan (unchanged)
// ---------------------------------------------------------------------------
__global__ __launch_bounds__(256) void scanA_kernel(const float* __restrict__ gates) {
    int t = blockIdx.x * 256 + threadIdx.x;
    int d = t & 63, rest = t >> 6;
    int b = rest & 255, ch = rest >> 8;
    const size_t S = (size_t)Mseq * 64;
    size_t base = ((size_t)(b * Lm + ch * CL)) * 64 + d;
    float c = 0.f, P = 1.f;
    #pragma unroll 5
    for (int l = 0; l < CL; l++) {
        size_t idx = base + (size_t)l * 64;
        float i_ = gates[idx];
        float f_ = gates[S + idx];
        float z_ = gates[2 * S + idx];
        c = f_ * c + i_ * z_;
        P *= f_;
    }
    g_scanA[t] = c;
    g_scanP[t] = P;
}

__global__ __launch_bounds__(256) void scanB_kernel() {
    int t = blockIdx.x * 256 + threadIdx.x;
    float c = 0.f;
    #pragma unroll
    for (int ch = 0; ch < NC; ch++) {
        int q = ch * 16384 + t;
        g_scanCin[q] = c;
        c = g_scanP[q] * c + g_scanA[q];
    }
    g_Clast[t] = c;
}

__global__ __launch_bounds__(256) void scanC_kernel(const float* __restrict__ gates,
                                                    const float* __restrict__ days) {
    int t = blockIdx.x * 256 + threadIdx.x;
    int d = t & 63, rest = t >> 6;
    int b = rest & 255, ch = rest >> 8;
    const size_t S = (size_t)Mseq * 64;
    size_t base = ((size_t)(b * Lm + ch * CL)) * 64 + d;
    const float* dptr = days + b * Lm + ch * CL;
    float c = g_scanCin[t];
    #pragma unroll 5
    for (int l = 0; l < CL; l++) {
        size_t idx = base + (size_t)l * 64;
        float i_ = gates[idx];
        float f_ = gates[S + idx];
        float z_ = gates[2 * S + idx];
        float o_ = gates[3 * S + idx];
        float dl = gates[4 * S + idx];
        float cb = gates[5 * S + idx];
        float dt = fmaxf(dptr[l], 0.f);
        c = f_ * c + i_ * z_;
        float e = __expf(-dl * dt);
        float cd = cb + (c - cb) * e;
        g_Hs[idx] = o_ * fast_tanh(cd);
    }
}

// ---------------------------------------------------------------------------
// Final CT-LSTM step at dt = 0
// ---------------------------------------------------------------------------
__global__ void final_ch_kernel() {
    int b = blockIdx.x, d = threadIdx.x;
    const int S = Bm * 64;
    int idx = b * 64 + d;
    float c = g_Gc[S + idx] * g_Clast[idx] + g_Gc[idx] * g_Gc[2 * S + idx];
    g_Hcur[idx] = g_Gc[3 * S + idx] * fast_tanh(c);
}

// ---------------------------------------------------------------------------
// Intensity MLP (unchanged; Ys aliased into rows buffer)
// ---------------------------------------------------------------------------
__global__ __launch_bounds__(256) void intensity_kernel(const float* __restrict__ src, int M,
                                                        const float* __restrict__ W1,
                                                        const float* __restrict__ b1,
                                                        const float* __restrict__ W2,
                                                        const float* __restrict__ b2,
                                                        float* __restrict__ out) {
    __shared__ __align__(16) float rows[128][68];
    __shared__ __align__(16) float W1s[2048];
    __shared__ float W2s[192], b1s[32], b2s[6];
    float* Ys = &rows[0][0];
    int tid = threadIdx.x;
    size_t r0 = (size_t)blockIdx.x * 128;

    for (int i4 = tid; i4 < 512; i4 += 256)
        *reinterpret_cast<float4*>(&W1s[i4 * 4]) = reinterpret_cast<const float4*>(W1)[i4];
    if (tid < 192) W2s[tid] = W2[tid];
    if (tid < 32) b1s[tid] = b1[tid];
    if (tid < 6) b2s[tid] = b2[tid];
    #pragma unroll
    for (int p = 0; p < 8; p++) {
        int idx = tid + p * 256;
        int m = idx >> 4, dv = (idx & 15) * 4;
        *reinterpret_cast<float4*>(&rows[m][dv]) =
            *reinterpret_cast<const float4*>(src + (r0 + m) * 64 + dv);
    }
    __syncthreads();

    int tr = tid >> 3, tc = tid & 7;
    float acc[4][4];
    #pragma unroll
    for (int i = 0; i < 4; i++)
        #pragma unroll
        for (int j = 0; j < 4; j++) acc[i][j] = b1s[tc * 4 + j];
    #pragma unroll 4
    for (int k = 0; k < 64; k++) {
        float4 w = *reinterpret_cast<const float4*>(&W1s[k * 32 + tc * 4]);
        float a0 = rows[tr * 4 + 0][k];
        float a1 = rows[tr * 4 + 1][k];
        float a2 = rows[tr * 4 + 2][k];
        float a3 = rows[tr * 4 + 3][k];
        acc[0][0] = fmaf(a0, w.x, acc[0][0]); acc[0][1] = fmaf(a0, w.y, acc[0][1]);
        acc[0][2] = fmaf(a0, w.z, acc[0][2]); acc[0][3] = fmaf(a0, w.w, acc[0][3]);
        acc[1][0] = fmaf(a1, w.x, acc[1][0]); acc[1][1] = fmaf(a1, w.y, acc[1][1]);
        acc[1][2] = fmaf(a1, w.z, acc[1][2]); acc[1][3] = fmaf(a1, w.w, acc[1][3]);
        acc[2][0] = fmaf(a2, w.x, acc[2][0]); acc[2][1] = fmaf(a2, w.y, acc[2][1]);
        acc[2][2] = fmaf(a2, w.z, acc[2][2]); acc[2][3] = fmaf(a2, w.w, acc[2][3]);
        acc[3][0] = fmaf(a3, w.x, acc[3][0]); acc[3][1] = fmaf(a3, w.y, acc[3][1]);
        acc[3][2] = fmaf(a3, w.z, acc[3][2]); acc[3][3] = fmaf(a3, w.w, acc[3][3]);
    }
    __syncthreads();
    #pragma unroll
    for (int i = 0; i < 4; i++)
        #pragma unroll
        for (int j = 0; j < 4; j++)
            Ys[(tr * 4 + i) * 33 + tc * 4 + j] = fgelu(acc[i][j]);
    __syncthreads();

    if (tid < 128) {
        int row = tid;
        float o6[6];
        #pragma unroll
        for (int c = 0; c < 6; c++) o6[c] = b2s[c];
        #pragma unroll 4
        for (int k = 0; k < 32; k++) {
            float a = Ys[row * 33 + k];
            #pragma unroll
            for (int c = 0; c < 6; c++) o6[c] = fmaf(a, W2s[k * 6 + c], o6[c]);
        }
        #pragma unroll
        for (int c = 0; c < 6; c++) out[(r0 + row) * 6 + c] = fsoftplus(o6[c]);
    }
}

// ---------------------------------------------------------------------------
// TTE head (unchanged)
// ---------------------------------------------------------------------------
__global__ __launch_bounds__(256) void tte_kernel(const float* __restrict__ W1,
                                                  const float* __restrict__ b1,
                                                  const float* __restrict__ W2,
                                                  const float* __restrict__ b2,
                                                  float* __restrict__ out) {
    __shared__ float W1s[64 * 32];
    __shared__ float W2s[32];
    __shared__ float b1s[32];
    __shared__ float b2s0;
    __shared__ float rows[8][64];
    int tid = threadIdx.x;
    for (int i = tid; i < 2048; i += 256) W1s[i] = W1[i];
    if (tid < 32) { W2s[tid] = W2[tid]; b1s[tid] = b1[tid]; }
    if (tid == 0) b2s0 = b2[0];
    __syncthreads();
    int warp = tid >> 5, lane = tid & 31;
    int b = blockIdx.x * 8 + warp;
    if (b >= Bm) return;
    rows[warp][lane] = g_Hcur[b * 64 + lane];
    rows[warp][lane + 32] = g_Hcur[b * 64 + lane + 32];
    __syncwarp();
    float acc = b1s[lane];
    #pragma unroll
    for (int k = 0; k < 64; k++) acc = fmaf(rows[warp][k], W1s[k * 32 + lane], acc);
    float y = fgelu(acc);
    float p = y * W2s[lane];
    #pragma unroll
    for (int off = 16; off; off >>= 1) p += __shfl_xor_sync(0xffffffffu, p, off);
    if (lane == 0) out[b] = fsoftplus(p + b2s0);
}

// ---------------------------------------------------------------------------
// Direct head + softmax (unchanged)
// ---------------------------------------------------------------------------
__global__ __launch_bounds__(384) void direct_kernel(const float* __restrict__ cls,
                                                     const float* __restrict__ Ws1,
                                                     const float* __restrict__ bs1,
                                                     const float* __restrict__ Ws2,
                                                     const float* __restrict__ bs2,
                                                     const float* __restrict__ ci,
                                                     float* __restrict__ probs) {
    __shared__ float cls_s[4 * 768];
    __shared__ float s1[4][384];
    __shared__ float logit_s[4][6];
    int tid = threadIdx.x;
    int b0 = blockIdx.x * 4;
    for (int idx = tid; idx < 4 * 768; idx += 384)
        cls_s[idx] = cls[(size_t)b0 * 768 + idx];
    __syncthreads();
    float a0 = bs1[tid], a1 = a0, a2 = a0, a3 = a0;
    #pragma unroll 4
    for (int k = 0; k < 768; k++) {
        float w = Ws1[(size_t)k * 384 + tid];
        a0 = fmaf(cls_s[k], w, a0);
        a1 = fmaf(cls_s[768 + k], w, a1);
        a2 = fmaf(cls_s[1536 + k], w, a2);
        a3 = fmaf(cls_s[2304 + k], w, a3);
    }
    s1[0][tid] = fgelu(a0);
    s1[1][tid] = fgelu(a1);
    s1[2][tid] = fgelu(a2);
    s1[3][tid] = fgelu(a3);
    __syncthreads();
    int w = tid >> 5, lane = tid & 31;
    if (w < 6) {
        for (int g = 0; g < 4; g++) {
            float p = 0.f;
            #pragma unroll
            for (int j = lane; j < 384; j += 32) p = fmaf(s1[g][j], Ws2[(size_t)j * 6 + w], p);
            #pragma unroll
            for (int off = 16; off; off >>= 1) p += __shfl_xor_sync(0xffffffffu, p, off);
            if (lane == 0) logit_s[g][w] = p + bs2[w];
        }
    }
    __syncthreads();
    if (tid < 4) {
        int g = tid;
        float x[6], m = -1e30f;
        #pragma unroll
        for (int c = 0; c < 6; c++) {
            x[c] = logit_s[g][c] + logf(ci[(size_t)(b0 + g) * 6 + c]);
            m = fmaxf(m, x[c]);
        }
        float s = 0.f;
        #pragma unroll
        for (int c = 0; c < 6; c++) { x[c] = __expf(x[c] - m); s += x[c]; }
        float inv = __fdividef(1.f, s);
        #pragma unroll
        for (int c = 0; c < 6; c++) probs[(size_t)(b0 + g) * 6 + c] = x[c] * inv;
    }
}

// ---------------------------------------------------------------------------
// Launch
// ---------------------------------------------------------------------------
extern "C" void kernel_launch(void* const* d_in, const int* in_sizes, int n_in,
                              void* d_out, int out_size) {
    const float* cls   = (const float*)d_in[0];
    const float* ev    = (const float*)d_in[1];
    const float* days  = (const float*)d_in[2];
    const float* We    = (const float*)d_in[3];
    const float* be    = (const float*)d_in[4];
    const float* Wtime = (const float*)d_in[5];
    const float* btime = (const float*)d_in[6];
    const float* Wg    = (const float*)d_in[7];
    const float* bg    = (const float*)d_in[8];
    const float* Wi1   = (const float*)d_in[9];
    const float* bi1   = (const float*)d_in[10];
    const float* Wi2   = (const float*)d_in[11];
    const float* bi2   = (const float*)d_in[12];
    const float* Ws1   = (const float*)d_in[13];
    const float* bs1   = (const float*)d_in[14];
    const float* Ws2   = (const float*)d_in[15];
    const float* bs2   = (const float*)d_in[16];
    const float* Wq1   = (const float*)d_in[17];
    const float* bq1   = (const float*)d_in[18];
    const float* Wq2   = (const float*)d_in[19];
    const float* bq2   = (const float*)d_in[20];

    float* out = (float*)d_out;
    float* out_probs = out;
    float* out_tte   = out + 1536;
    float* out_ci    = out + 1536 + 256;
    float* out_hist  = out + 1536 + 256 + 1536;

    float *pE, *pG, *pEc, *pGc, *pHs, *pHcur;
    unsigned *pWeHi, *pWeLo, *pWgHi, *pWgLo;
    cudaGetSymbolAddress((void**)&pE, g_E);
    cudaGetSymbolAddress((void**)&pG, g_G);
    cudaGetSymbolAddress((void**)&pEc, g_Ec);
    cudaGetSymbolAddress((void**)&pGc, g_Gc);
    cudaGetSymbolAddress((void**)&pHs, g_Hs);
    cudaGetSymbolAddress((void**)&pHcur, g_Hcur);
    cudaGetSymbolAddress((void**)&pWeHi, g_WeHi);
    cudaGetSymbolAddress((void**)&pWeLo, g_WeLo);
    cudaGetSymbolAddress((void**)&pWgHi, g_WgHi);
    cudaGetSymbolAddress((void**)&pWgLo, g_WgLo);

    setup_kernel<<<1, 384>>>(Wtime, btime, Wg, bg);
    split_we_kernel<<<96, 256>>>(We);
    split_wg_kernel<<<48, 256>>>(Wg);

    gemm1_mma<<<NEVB + 2, 256>>>(ev, cls, pWeHi, pWeLo, be, pE, pEc);
    gemm2_mma<<<dim3(NEVB + 2, 3), 256>>>(pE, pEc, pWgHi, pWgLo, days, pG, pGc);

    scanA_kernel<<<(Bm * Dm * NC) / 256, 256>>>(pG);
    scanB_kernel<<<(Bm * Dm) / 256, 256>>>();
    scanC_kernel<<<(Bm * Dm * NC) / 256, 256>>>(pG, days);
    final_ch_kernel<<<Bm, 64>>>();

    intensity_kernel<<<Mseq / 128, 256>>>(pHs, Mseq, Wi1, bi1, Wi2, bi2, out_hist);
    intensity_kernel<<<Bm / 128, 256>>>(pHcur, Bm, Wi1, bi1, Wi2, bi2, out_ci);
    tte_kernel<<<Bm / 8, 256>>>(Wq1, bq1, Wq2, bq2, out_tte);
    direct_kernel<<<Bm / 4, 384>>>(cls, Ws1, bs1, Ws2, bs2, out_ci, out_probs);
}